// round 9
// baseline (speedup 1.0000x reference)
#include <cuda_runtime.h>

#define NN 50000
#define EE 800000
#define IND 128
#define HD 64
#define TOTE (EE + NN)
#define NB_SCAN 196   // ceil(NN/256)

// ---------------- scratch (static device memory; no allocations) ----------------
__device__ __align__(256) float d_h[NN * HD];
__device__ __align__(256) float d_x1[NN * HD];
__device__ __align__(256) float d_x2[NN * HD];
__device__ __align__(256) float d_proj[NN * HD];
__device__ __align__(256) float d_as[NN];
__device__ __align__(256) float d_ad[NN];
__device__ __align__(256) float d_gsum[HD];
__device__ __align__(256) int   d_cnt[NN];
__device__ __align__(256) int   d_roff[NN];
__device__ __align__(256) int   d_fill[NN];
__device__ __align__(256) int   d_bsum[NB_SCAN];
__device__ __align__(256) int   d_esrc[TOTE];
// W fragments for mma: [mat(8)][ks(8)][lane(32)][32 floats: 16 hi, 16 lo]
__device__ __align__(256) float d_wfrag[8 * 8 * 32 * 32];

// ---------------- tf32 helpers ----------------
__device__ __forceinline__ unsigned cvt_tf32(float x) {
    unsigned r;
    asm("cvt.rna.tf32.f32 %0, %1;" : "=r"(r) : "f"(x));
    return r;
}
__device__ __forceinline__ void mma_tf32(float* c, unsigned a0, unsigned a1,
                                         unsigned a2, unsigned a3, unsigned b0,
                                         unsigned b1) {
    asm("mma.sync.aligned.m16n8k8.row.col.f32.tf32.tf32.f32 "
        "{%0,%1,%2,%3},{%4,%5,%6,%7},{%8,%9},{%0,%1,%2,%3};"
        : "+f"(c[0]), "+f"(c[1]), "+f"(c[2]), "+f"(c[3])
        : "r"(a0), "r"(a1), "r"(a2), "r"(a3), "r"(b0), "r"(b1));
}

// ---------------- CSR build ----------------
__global__ void __launch_bounds__(256) zero_cf(int* __restrict__ cnt,
                                               int* __restrict__ fill) {
    int i = blockIdx.x * blockDim.x + threadIdx.x;
    if (i < NN) { cnt[i] = 0; fill[i] = 0; }
}

__global__ void __launch_bounds__(256) hist(const int* __restrict__ dst,
                                            int* __restrict__ cnt) {
    int i = blockIdx.x * blockDim.x + threadIdx.x;
    if (i >= TOTE) return;
    int d = (i < EE) ? dst[i] : (i - EE);
    atomicAdd(&cnt[d], 1);
}

__global__ void __launch_bounds__(256) scan1(const int* __restrict__ cnt,
                                             int* __restrict__ roff,
                                             int* __restrict__ bsum) {
    __shared__ int sh[256];
    int t = threadIdx.x;
    int i = blockIdx.x * 256 + t;
    int v = (i < NN) ? cnt[i] : 0;
    sh[t] = v;
    __syncthreads();
#pragma unroll
    for (int o = 1; o < 256; o <<= 1) {
        int u = (t >= o) ? sh[t - o] : 0;
        __syncthreads();
        sh[t] += u;
        __syncthreads();
    }
    if (i < NN) roff[i] = sh[t] - v;           // exclusive
    if (t == 255) bsum[blockIdx.x] = sh[255];  // block total
}

__global__ void __launch_bounds__(256) scan2(int* __restrict__ bsum) {
    __shared__ int sh[256];
    int t = threadIdx.x;
    int v = (t < NB_SCAN) ? bsum[t] : 0;
    sh[t] = v;
    __syncthreads();
#pragma unroll
    for (int o = 1; o < 256; o <<= 1) {
        int u = (t >= o) ? sh[t - o] : 0;
        __syncthreads();
        sh[t] += u;
        __syncthreads();
    }
    if (t < NB_SCAN) bsum[t] = sh[t] - v;      // exclusive over blocks
}

__global__ void __launch_bounds__(256) scan3(int* __restrict__ roff,
                                             const int* __restrict__ bsum) {
    int i = blockIdx.x * blockDim.x + threadIdx.x;
    if (i < NN) roff[i] += bsum[i >> 8];
}

__global__ void __launch_bounds__(256) scatter(const int* __restrict__ src,
                                               const int* __restrict__ dst,
                                               const int* __restrict__ roff,
                                               int* __restrict__ fill,
                                               int* __restrict__ esrc) {
    int i = blockIdx.x * blockDim.x + threadIdx.x;
    if (i >= TOTE) return;
    int s, d;
    if (i < EE) { s = src[i]; d = dst[i]; } else { s = d = i - EE; }
    int pos = roff[d] + atomicAdd(&fill[d], 1);
    esrc[pos] = s;
}

// ---------------- prep W fragments (hi/lo tf32, fragment-ordered) ----------
__global__ void __launch_bounds__(256) prep_w(const float* __restrict__ convW,
                                              const float* __restrict__ projW,
                                              float* __restrict__ wf) {
    int i = blockIdx.x * 256 + threadIdx.x;  // 0..32767
    if (i >= 8 * 8 * 32 * 16) return;
    int j = i & 1;
    int nt = (i >> 1) & 7;
    int lane = (i >> 4) & 31;
    int ks = (i >> 9) & 7;
    int mat = i >> 12;
    int tid = lane & 3, gid = lane >> 2;
    const float* W = (mat < 4) ? convW + mat * HD * HD : projW + (mat - 4) * HD * HD;
    float v = W[(ks * 8 + tid + j * 4) * HD + nt * 8 + gid];
    unsigned hb = cvt_tf32(v);
    float lo = v - __uint_as_float(hb);
    unsigned lb = cvt_tf32(lo);
    float* base = wf + ((size_t)(mat * 8 + ks) * 32 + lane) * 32;
    base[nt * 2 + j] = __uint_as_float(hb);
    base[16 + nt * 2 + j] = __uint_as_float(lb);
}

// ---------------- layer-1 GEMM (K=128) + fused scores (scalar, R7) ----------
__global__ void __launch_bounds__(256) gemm1(const float* __restrict__ X,
                                             const float* __restrict__ W,
                                             float* __restrict__ Y,
                                             const float* __restrict__ a_s,
                                             const float* __restrict__ a_d,
                                             float* __restrict__ as_o,
                                             float* __restrict__ ad_o) {
    __shared__ float Ws[IND * HD];   // 32KB
    __shared__ float Xs[16 * IND];   // 8KB
    int t = threadIdx.x;
    for (int i = t; i < IND * HD; i += 256) Ws[i] = W[i];
    int nb = blockIdx.x * 16;
    for (int i = t; i < 16 * IND; i += 256) {
        int r = i >> 7, c = i & 127;
        int node = nb + r;
        Xs[i] = (node < NN) ? X[(size_t)node * IND + c] : 0.f;
    }
    __syncthreads();
    int cp = t & 31, g = t >> 5;
    float2 a0 = make_float2(0.f, 0.f), a1 = make_float2(0.f, 0.f);
#pragma unroll 8
    for (int k = 0; k < IND; k++) {
        float2 w = reinterpret_cast<const float2*>(Ws)[k * 32 + cp];
        float x0 = Xs[(g * 2 + 0) * IND + k];
        float x1 = Xs[(g * 2 + 1) * IND + k];
        a0.x += x0 * w.x; a0.y += x0 * w.y;
        a1.x += x1 * w.x; a1.y += x1 * w.y;
    }
    int r0 = nb + g * 2;
    if (r0 < NN)
        reinterpret_cast<float2*>(Y)[(size_t)r0 * 32 + cp] = a0;
    if (r0 + 1 < NN)
        reinterpret_cast<float2*>(Y)[(size_t)(r0 + 1) * 32 + cp] = a1;
    float2 sv = reinterpret_cast<const float2*>(a_s)[cp];
    float2 dv = reinterpret_cast<const float2*>(a_d)[cp];
    float s0 = a0.x * sv.x + a0.y * sv.y;
    float s1 = a1.x * sv.x + a1.y * sv.y;
    float d0 = a0.x * dv.x + a0.y * dv.y;
    float d1 = a1.x * dv.x + a1.y * dv.y;
#pragma unroll
    for (int o = 16; o; o >>= 1) {
        s0 += __shfl_xor_sync(0xffffffffu, s0, o);
        s1 += __shfl_xor_sync(0xffffffffu, s1, o);
        d0 += __shfl_xor_sync(0xffffffffu, d0, o);
        d1 += __shfl_xor_sync(0xffffffffu, d1, o);
    }
    if ((t & 31) == 0) {
        if (r0 < NN) { as_o[r0] = s0; ad_o[r0] = d0; }
        if (r0 + 1 < NN) { as_o[r0 + 1] = s1; ad_o[r0 + 1] = d1; }
    }
}

// ---------------- dual GEMM via tf32 mma (split hi/lo): Y=X@Wc (+scores), P=X@Wp
// block = 256 (8 warps); each warp: 16 rows x 64 cols, both matrices.
__global__ void __launch_bounds__(256) gemm_dual_mma(
    const float* __restrict__ X, const float* __restrict__ wf_c,
    const float* __restrict__ wf_p, float* __restrict__ Y,
    float* __restrict__ P, const float* __restrict__ a_s,
    const float* __restrict__ a_d, float* __restrict__ as_o,
    float* __restrict__ ad_o) {
    __shared__ float Xs[128 * 68];   // padded stride 68: conflict-free A frags
    __shared__ float as_sh[HD], ad_sh[HD];
    int t = threadIdx.x;
    int nb = blockIdx.x * 128;
    for (int i = t; i < 128 * 64; i += 256) {
        int r = i >> 6, c = i & 63;
        int node = nb + r;
        Xs[r * 68 + c] = (node < NN) ? X[(size_t)node * HD + c] : 0.f;
    }
    if (t < HD) { as_sh[t] = a_s[t]; ad_sh[t] = a_d[t]; }
    __syncthreads();
    int w = t >> 5, lane = t & 31;
    int r0 = nb + w * 16;
    if (r0 >= NN) return;   // warp-granular tail (NN % 16 == 0)
    int tid = lane & 3, gid = lane >> 2;
    float cc[8][4], cp_[8][4];
#pragma unroll
    for (int n = 0; n < 8; n++)
#pragma unroll
        for (int q = 0; q < 4; q++) { cc[n][q] = 0.f; cp_[n][q] = 0.f; }
    int rA0 = (w * 16 + gid) * 68, rA1 = (w * 16 + gid + 8) * 68;
#pragma unroll
    for (int ks = 0; ks < 8; ks++) {
        int c0i = ks * 8 + tid;
        float x0 = Xs[rA0 + c0i];
        float x1 = Xs[rA1 + c0i];
        float x2 = Xs[rA0 + c0i + 4];
        float x3 = Xs[rA1 + c0i + 4];
        unsigned ah0 = cvt_tf32(x0), ah1 = cvt_tf32(x1);
        unsigned ah2 = cvt_tf32(x2), ah3 = cvt_tf32(x3);
        unsigned al0 = cvt_tf32(x0 - __uint_as_float(ah0));
        unsigned al1 = cvt_tf32(x1 - __uint_as_float(ah1));
        unsigned al2 = cvt_tf32(x2 - __uint_as_float(ah2));
        unsigned al3 = cvt_tf32(x3 - __uint_as_float(ah3));
        // ---- conv matrix ----
        {
            const float4* pb =
                reinterpret_cast<const float4*>(wf_c + ((size_t)(ks * 32) + lane) * 32);
            float H[16], L[16];
            *reinterpret_cast<float4*>(H + 0) = pb[0];
            *reinterpret_cast<float4*>(H + 4) = pb[1];
            *reinterpret_cast<float4*>(H + 8) = pb[2];
            *reinterpret_cast<float4*>(H + 12) = pb[3];
            *reinterpret_cast<float4*>(L + 0) = pb[4];
            *reinterpret_cast<float4*>(L + 4) = pb[5];
            *reinterpret_cast<float4*>(L + 8) = pb[6];
            *reinterpret_cast<float4*>(L + 12) = pb[7];
#pragma unroll
            for (int nt = 0; nt < 8; nt++) {
                unsigned bh0 = __float_as_uint(H[nt * 2 + 0]);
                unsigned bh1 = __float_as_uint(H[nt * 2 + 1]);
                unsigned bl0 = __float_as_uint(L[nt * 2 + 0]);
                unsigned bl1 = __float_as_uint(L[nt * 2 + 1]);
                mma_tf32(cc[nt], ah0, ah1, ah2, ah3, bh0, bh1);
                mma_tf32(cc[nt], ah0, ah1, ah2, ah3, bl0, bl1);
                mma_tf32(cc[nt], al0, al1, al2, al3, bh0, bh1);
            }
        }
        // ---- proj matrix ----
        {
            const float4* pb =
                reinterpret_cast<const float4*>(wf_p + ((size_t)(ks * 32) + lane) * 32);
            float H[16], L[16];
            *reinterpret_cast<float4*>(H + 0) = pb[0];
            *reinterpret_cast<float4*>(H + 4) = pb[1];
            *reinterpret_cast<float4*>(H + 8) = pb[2];
            *reinterpret_cast<float4*>(H + 12) = pb[3];
            *reinterpret_cast<float4*>(L + 0) = pb[4];
            *reinterpret_cast<float4*>(L + 4) = pb[5];
            *reinterpret_cast<float4*>(L + 8) = pb[6];
            *reinterpret_cast<float4*>(L + 12) = pb[7];
#pragma unroll
            for (int nt = 0; nt < 8; nt++) {
                unsigned bh0 = __float_as_uint(H[nt * 2 + 0]);
                unsigned bh1 = __float_as_uint(H[nt * 2 + 1]);
                unsigned bl0 = __float_as_uint(L[nt * 2 + 0]);
                unsigned bl1 = __float_as_uint(L[nt * 2 + 1]);
                mma_tf32(cp_[nt], ah0, ah1, ah2, ah3, bh0, bh1);
                mma_tf32(cp_[nt], ah0, ah1, ah2, ah3, bl0, bl1);
                mma_tf32(cp_[nt], al0, al1, al2, al3, bh0, bh1);
            }
        }
    }
    // ---- stores: C layout c0,c1 -> (row gid, cols 2tid,2tid+1); c2,c3 -> row gid+8
    float2* Y2 = reinterpret_cast<float2*>(Y);
    float2* P2 = reinterpret_cast<float2*>(P);
    size_t ra = (size_t)(r0 + gid) * 32 + tid;
    size_t rb = (size_t)(r0 + gid + 8) * 32 + tid;
#pragma unroll
    for (int nt = 0; nt < 8; nt++) {
        Y2[ra + nt * 4] = make_float2(cc[nt][0], cc[nt][1]);
        Y2[rb + nt * 4] = make_float2(cc[nt][2], cc[nt][3]);
        P2[ra + nt * 4] = make_float2(cp_[nt][0], cp_[nt][1]);
        P2[rb + nt * 4] = make_float2(cp_[nt][2], cp_[nt][3]);
    }
    // ---- scores from conv C frags ----
    float s0 = 0.f, s1 = 0.f, dd0 = 0.f, dd1 = 0.f;
#pragma unroll
    for (int nt = 0; nt < 8; nt++) {
        float sa = as_sh[nt * 8 + 2 * tid], sb = as_sh[nt * 8 + 2 * tid + 1];
        float da = ad_sh[nt * 8 + 2 * tid], db = ad_sh[nt * 8 + 2 * tid + 1];
        s0 += cc[nt][0] * sa + cc[nt][1] * sb;
        s1 += cc[nt][2] * sa + cc[nt][3] * sb;
        dd0 += cc[nt][0] * da + cc[nt][1] * db;
        dd1 += cc[nt][2] * da + cc[nt][3] * db;
    }
    s0 += __shfl_xor_sync(0xffffffffu, s0, 1);
    s0 += __shfl_xor_sync(0xffffffffu, s0, 2);
    s1 += __shfl_xor_sync(0xffffffffu, s1, 1);
    s1 += __shfl_xor_sync(0xffffffffu, s1, 2);
    dd0 += __shfl_xor_sync(0xffffffffu, dd0, 1);
    dd0 += __shfl_xor_sync(0xffffffffu, dd0, 2);
    dd1 += __shfl_xor_sync(0xffffffffu, dd1, 1);
    dd1 += __shfl_xor_sync(0xffffffffu, dd1, 2);
    if (tid == 0) {
        as_o[r0 + gid] = s0;
        ad_o[r0 + gid] = dd0;
        as_o[r0 + gid + 8] = s1;
        ad_o[r0 + gid + 8] = dd1;
    }
}

// ---------------- fused gather-aggregate + softmax + bias/relu/bn(+proj) ------
template <bool PROJ>
__global__ void __launch_bounds__(256) agg_post(
    const int* __restrict__ roff, const int* __restrict__ cnt,
    const int* __restrict__ esrc, const float* __restrict__ as_,
    const float* __restrict__ ad_, const float* __restrict__ h,
    const float* __restrict__ bias, const float* __restrict__ bg,
    const float* __restrict__ bb, const float* __restrict__ bm,
    const float* __restrict__ bv, const float* __restrict__ proj,
    const float* __restrict__ projb, float* __restrict__ out) {
    int node = (blockIdx.x * blockDim.x + threadIdx.x) >> 5;
    int lane = threadIdx.x & 31;
    if (node >= NN) return;
    int beg = roff[node];
    int m = cnt[node];
    float adn = ad_[node];
    const float4* __restrict__ h4 = reinterpret_cast<const float4*>(h);
    int q = lane & 15, half = lane >> 4;
    float ax = 0.f, ay = 0.f, az = 0.f, aw = 0.f, denom = 0.f;
    for (int base = 0; base < m; base += 32) {
        int rem = m - base;
        int nn = rem < 32 ? rem : 32;
        int s_l = 0;
        float ex_l = 0.f;
        if (lane < nn) {
            s_l = esrc[beg + base + lane];
            float e = as_[s_l] + adn;
            e = e > 0.f ? e : 0.2f * e;
            ex_l = __expf(e);
        }
        denom += ex_l;
#pragma unroll 2
        for (int j = 0; j < nn; j += 2) {
            int jj = j + half;
            int s = __shfl_sync(0xffffffffu, s_l, jj & 31);
            float ex = __shfl_sync(0xffffffffu, ex_l, jj & 31);
            if (jj < nn) {
                float4 hv = h4[(size_t)s * 16 + q];
                ax += ex * hv.x;
                ay += ex * hv.y;
                az += ex * hv.z;
                aw += ex * hv.w;
            }
        }
    }
    ax += __shfl_xor_sync(0xffffffffu, ax, 16);
    ay += __shfl_xor_sync(0xffffffffu, ay, 16);
    az += __shfl_xor_sync(0xffffffffu, az, 16);
    aw += __shfl_xor_sync(0xffffffffu, aw, 16);
#pragma unroll
    for (int o = 16; o; o >>= 1) denom += __shfl_xor_sync(0xffffffffu, denom, o);
    if (half == 0) {
        float inv = 1.f / (denom + 1e-16f);
        float4 b4 = reinterpret_cast<const float4*>(bias)[q];
        float4 g4 = reinterpret_cast<const float4*>(bg)[q];
        float4 be4 = reinterpret_cast<const float4*>(bb)[q];
        float4 m4 = reinterpret_cast<const float4*>(bm)[q];
        float4 v4 = reinterpret_cast<const float4*>(bv)[q];
        float vx = fmaxf(ax * inv + b4.x, 0.f);
        float vy = fmaxf(ay * inv + b4.y, 0.f);
        float vz = fmaxf(az * inv + b4.z, 0.f);
        float vw = fmaxf(aw * inv + b4.w, 0.f);
        vx = (vx - m4.x) * rsqrtf(v4.x + 1e-5f) * g4.x + be4.x;
        vy = (vy - m4.y) * rsqrtf(v4.y + 1e-5f) * g4.y + be4.y;
        vz = (vz - m4.z) * rsqrtf(v4.z + 1e-5f) * g4.z + be4.z;
        vw = (vw - m4.w) * rsqrtf(v4.w + 1e-5f) * g4.w + be4.w;
        if (PROJ) {
            float4 p4 = reinterpret_cast<const float4*>(proj)[(size_t)node * 16 + q];
            float4 pb4 = reinterpret_cast<const float4*>(projb)[q];
            vx += p4.x + pb4.x;
            vy += p4.y + pb4.y;
            vz += p4.z + pb4.z;
            vw += p4.w + pb4.w;
        }
        reinterpret_cast<float4*>(out)[(size_t)node * 16 + q] =
            make_float4(vx, vy, vz, vw);
    }
}

// ---------------- mean pool ----------------
__global__ void zero_gsum(float* __restrict__ g) {
    if (threadIdx.x < HD) g[threadIdx.x] = 0.f;
}
__global__ void __launch_bounds__(256) pool(const float* __restrict__ xp,
                                            float* __restrict__ gsum) {
    int t = threadIdx.x;
    int c = t & 63;
    int row0 = blockIdx.x * 4 + (t >> 6);
    float acc = 0.f;
    for (int n = row0; n < NN; n += gridDim.x * 4) acc += xp[(size_t)n * HD + c];
    atomicAdd(&gsum[c], acc);
}

// ---------------- head MLP ----------------
__global__ void head(const float* __restrict__ gsum, const float* __restrict__ hW1,
                     const float* __restrict__ hb1, const float* __restrict__ hg,
                     const float* __restrict__ hb, const float* __restrict__ hm,
                     const float* __restrict__ hv, const float* __restrict__ hW2,
                     const float* __restrict__ hb2, float* __restrict__ out) {
    __shared__ float g[HD];
    int t = threadIdx.x;
    if (t < HD) g[t] = gsum[t] * (1.f / NN);
    __syncthreads();
    float r = 0.f;
    if (t < 32) {
        float acc = hb1[t];
#pragma unroll
        for (int k = 0; k < HD; k++) acc += g[k] * hW1[k * 32 + t];
        acc = fmaxf(acc, 0.f);
        acc = (acc - hm[t]) * rsqrtf(hv[t] + 1e-5f) * hg[t] + hb[t];
        r = acc * hW2[t];
#pragma unroll
        for (int o = 16; o; o >>= 1) r += __shfl_xor_sync(0xffffffffu, r, o);
        if (t == 0) out[0] = r + hb2[0];
    }
}

// ---------------- launch ----------------
extern "C" void kernel_launch(void* const* d_in, const int* in_sizes, int n_in,
                              void* d_out, int out_size) {
    (void)in_sizes; (void)n_in; (void)out_size;
    const float* x        = (const float*)d_in[0];
    const int*   ei       = (const int*)d_in[1];
    const float* conv1_W  = (const float*)d_in[2];
    const float* conv1_as = (const float*)d_in[3];
    const float* conv1_ad = (const float*)d_in[4];
    const float* conv1_b  = (const float*)d_in[5];
    const float* convW    = (const float*)d_in[6];
    const float* conv_as  = (const float*)d_in[7];
    const float* conv_ad  = (const float*)d_in[8];
    const float* conv_b   = (const float*)d_in[9];
    const float* bn_g     = (const float*)d_in[10];
    const float* bn_b     = (const float*)d_in[11];
    const float* bn_m     = (const float*)d_in[12];
    const float* bn_v     = (const float*)d_in[13];
    const float* projW    = (const float*)d_in[14];
    const float* projb    = (const float*)d_in[15];
    const float* hW1      = (const float*)d_in[16];
    const float* hb1      = (const float*)d_in[17];
    const float* hbn_g    = (const float*)d_in[18];
    const float* hbn_b    = (const float*)d_in[19];
    const float* hbn_m    = (const float*)d_in[20];
    const float* hbn_v    = (const float*)d_in[21];
    const float* hW2      = (const float*)d_in[22];
    const float* hb2      = (const float*)d_in[23];

    const int* src = ei;
    const int* dst = ei + EE;

    float *h, *x1, *x2, *proj, *as_, *ad_, *gsum, *wfrag;
    int *cnt, *roff, *fill, *bsum, *esrc;
    cudaGetSymbolAddress((void**)&h, d_h);
    cudaGetSymbolAddress((void**)&x1, d_x1);
    cudaGetSymbolAddress((void**)&x2, d_x2);
    cudaGetSymbolAddress((void**)&proj, d_proj);
    cudaGetSymbolAddress((void**)&as_, d_as);
    cudaGetSymbolAddress((void**)&ad_, d_ad);
    cudaGetSymbolAddress((void**)&gsum, d_gsum);
    cudaGetSymbolAddress((void**)&cnt, d_cnt);
    cudaGetSymbolAddress((void**)&roff, d_roff);
    cudaGetSymbolAddress((void**)&fill, d_fill);
    cudaGetSymbolAddress((void**)&bsum, d_bsum);
    cudaGetSymbolAddress((void**)&esrc, d_esrc);
    cudaGetSymbolAddress((void**)&wfrag, d_wfrag);

    const int G1 = (NN + 15) / 16;             // gemm1 blocks (16 rows)
    const int GM = (NN + 127) / 128;           // gemm_dual_mma blocks (128 rows)
    const int AB = (NN * 32 + 255) / 256;      // warp-per-node blocks
    const int NB = (NN + 255) / 256;           // node-sized blocks
    const int MB = (TOTE + 255) / 256;         // edge-sized blocks

    // ---- CSR build + W fragment prep ----
    zero_cf<<<NB, 256>>>(cnt, fill);
    hist<<<MB, 256>>>(dst, cnt);
    prep_w<<<128, 256>>>(convW, projW, wfrag);
    scan1<<<NB_SCAN, 256>>>(cnt, roff, bsum);
    scan2<<<1, 256>>>(bsum);
    scan3<<<NB_SCAN, 256>>>(roff, bsum);
    scatter<<<MB, 256>>>(src, dst, roff, fill, esrc);

    // ---- layer 1 ----
    gemm1<<<G1, 256>>>(x, conv1_W, h, conv1_as, conv1_ad, as_, ad_);
    agg_post<false><<<AB, 256>>>(roff, cnt, esrc, as_, ad_, h, conv1_b, bn_g,
                                 bn_b, bn_m, bn_v, nullptr, nullptr, x1);

    float* xp = x1;
    float* xn = x2;
    for (int l = 0; l < 4; l++) {
        const float* wf_c = wfrag + (size_t)l * 8 * 32 * 32;
        const float* wf_p = wfrag + (size_t)(4 + l) * 8 * 32 * 32;
        gemm_dual_mma<<<GM, 256>>>(xp, wf_c, wf_p, h, proj, conv_as + l * HD,
                                   conv_ad + l * HD, as_, ad_);
        agg_post<true><<<AB, 256>>>(roff, cnt, esrc, as_, ad_, h,
                                    conv_b + l * HD, bn_g + (l + 1) * HD,
                                    bn_b + (l + 1) * HD, bn_m + (l + 1) * HD,
                                    bn_v + (l + 1) * HD, proj, projb + l * HD,
                                    xn);
        float* tmp = xp; xp = xn; xn = tmp;
    }

    zero_gsum<<<1, 64>>>(gsum);
    pool<<<256, 256>>>(xp, gsum);
    head<<<1, 64>>>(gsum, hW1, hb1, hbn_g, hbn_b, hbn_m, hbn_v, hW2, hb2,
                    (float*)d_out);
}

// round 10
// speedup vs baseline: 1.1495x; 1.1495x over previous
#include <cuda_runtime.h>

#define NN 50000
#define EE 800000
#define IND 128
#define HD 64
#define TOTE (EE + NN)
#define NB_SCAN 196   // ceil(NN/256)

// ---------------- scratch (static device memory; no allocations) ----------------
__device__ __align__(256) float d_h[NN * HD];
__device__ __align__(256) float d_x1[NN * HD];
__device__ __align__(256) float d_x2[NN * HD];
__device__ __align__(256) float d_proj[NN * HD];
__device__ __align__(256) float d_as[NN];
__device__ __align__(256) float d_ad[NN];
__device__ __align__(256) float d_gsum[HD];
__device__ __align__(256) int   d_cnt[NN];
__device__ __align__(256) int   d_roff[NN];
__device__ __align__(256) int   d_fill[NN];
__device__ __align__(256) int   d_bsum[NB_SCAN];
__device__ __align__(256) int   d_esrc[TOTE];

// ---------------- CSR build ----------------
__global__ void __launch_bounds__(256) zero_cf(int* __restrict__ cnt,
                                               int* __restrict__ fill) {
    int i = blockIdx.x * blockDim.x + threadIdx.x;
    if (i < NN) { cnt[i] = 0; fill[i] = 0; }
}

__global__ void __launch_bounds__(256) hist(const int* __restrict__ dst,
                                            int* __restrict__ cnt) {
    int i = blockIdx.x * blockDim.x + threadIdx.x;
    if (i >= TOTE) return;
    int d = (i < EE) ? dst[i] : (i - EE);
    atomicAdd(&cnt[d], 1);
}

__global__ void __launch_bounds__(256) scan1(const int* __restrict__ cnt,
                                             int* __restrict__ roff,
                                             int* __restrict__ bsum) {
    __shared__ int sh[256];
    int t = threadIdx.x;
    int i = blockIdx.x * 256 + t;
    int v = (i < NN) ? cnt[i] : 0;
    sh[t] = v;
    __syncthreads();
#pragma unroll
    for (int o = 1; o < 256; o <<= 1) {
        int u = (t >= o) ? sh[t - o] : 0;
        __syncthreads();
        sh[t] += u;
        __syncthreads();
    }
    if (i < NN) roff[i] = sh[t] - v;           // exclusive
    if (t == 255) bsum[blockIdx.x] = sh[255];  // block total
}

__global__ void __launch_bounds__(256) scan2(int* __restrict__ bsum) {
    __shared__ int sh[256];
    int t = threadIdx.x;
    int v = (t < NB_SCAN) ? bsum[t] : 0;
    sh[t] = v;
    __syncthreads();
#pragma unroll
    for (int o = 1; o < 256; o <<= 1) {
        int u = (t >= o) ? sh[t - o] : 0;
        __syncthreads();
        sh[t] += u;
        __syncthreads();
    }
    if (t < NB_SCAN) bsum[t] = sh[t] - v;      // exclusive over blocks
}

__global__ void __launch_bounds__(256) scan3(int* __restrict__ roff,
                                             const int* __restrict__ bsum) {
    int i = blockIdx.x * blockDim.x + threadIdx.x;
    if (i < NN) roff[i] += bsum[i >> 8];
}

__global__ void __launch_bounds__(256) scatter(const int* __restrict__ src,
                                               const int* __restrict__ dst,
                                               const int* __restrict__ roff,
                                               int* __restrict__ fill,
                                               int* __restrict__ esrc) {
    int i = blockIdx.x * blockDim.x + threadIdx.x;
    if (i >= TOTE) return;
    int s, d;
    if (i < EE) { s = src[i]; d = dst[i]; } else { s = d = i - EE; }
    int pos = roff[d] + atomicAdd(&fill[d], 1);
    esrc[pos] = s;
}

// ---------------- layer-1 GEMM (K=128) + fused scores ----------------
// 256 threads: cp = t&31 (col pair), g = t>>5 (8 groups x 2 rows) -> 16 rows/blk
__global__ void __launch_bounds__(256) gemm1(const float* __restrict__ X,
                                             const float* __restrict__ W,
                                             float* __restrict__ Y,
                                             const float* __restrict__ a_s,
                                             const float* __restrict__ a_d,
                                             float* __restrict__ as_o,
                                             float* __restrict__ ad_o) {
    __shared__ float Ws[IND * HD];   // 32KB
    __shared__ float Xs[16 * IND];   // 8KB
    int t = threadIdx.x;
    for (int i = t; i < IND * HD; i += 256) Ws[i] = W[i];
    int nb = blockIdx.x * 16;
    for (int i = t; i < 16 * IND; i += 256) {
        int r = i >> 7, c = i & 127;
        int node = nb + r;
        Xs[i] = (node < NN) ? X[(size_t)node * IND + c] : 0.f;
    }
    __syncthreads();
    int cp = t & 31, g = t >> 5;
    float2 a0 = make_float2(0.f, 0.f), a1 = make_float2(0.f, 0.f);
#pragma unroll 8
    for (int k = 0; k < IND; k++) {
        float2 w = reinterpret_cast<const float2*>(Ws)[k * 32 + cp];
        float x0 = Xs[(g * 2 + 0) * IND + k];
        float x1 = Xs[(g * 2 + 1) * IND + k];
        a0.x += x0 * w.x; a0.y += x0 * w.y;
        a1.x += x1 * w.x; a1.y += x1 * w.y;
    }
    int r0 = nb + g * 2;
    if (r0 < NN)
        reinterpret_cast<float2*>(Y)[(size_t)r0 * 32 + cp] = a0;
    if (r0 + 1 < NN)
        reinterpret_cast<float2*>(Y)[(size_t)(r0 + 1) * 32 + cp] = a1;
    float2 sv = reinterpret_cast<const float2*>(a_s)[cp];
    float2 dv = reinterpret_cast<const float2*>(a_d)[cp];
    float s0 = a0.x * sv.x + a0.y * sv.y;
    float s1 = a1.x * sv.x + a1.y * sv.y;
    float d0 = a0.x * dv.x + a0.y * dv.y;
    float d1 = a1.x * dv.x + a1.y * dv.y;
#pragma unroll
    for (int o = 16; o; o >>= 1) {
        s0 += __shfl_xor_sync(0xffffffffu, s0, o);
        s1 += __shfl_xor_sync(0xffffffffu, s1, o);
        d0 += __shfl_xor_sync(0xffffffffu, d0, o);
        d1 += __shfl_xor_sync(0xffffffffu, d1, o);
    }
    if ((t & 31) == 0) {
        if (r0 < NN) { as_o[r0] = s0; ad_o[r0] = d0; }
        if (r0 + 1 < NN) { as_o[r0 + 1] = s1; ad_o[r0 + 1] = d1; }
    }
}

// ---------------- dual GEMM (K=64): Y = X@Wc (+scores), P = X@Wp ----------
// 256 threads: cp = t&31 (col pair), g = t>>5 (8 groups x 4 rows) -> 32 rows/blk
__global__ void __launch_bounds__(256) gemm_dual(const float* __restrict__ X,
                                                 const float* __restrict__ Wc,
                                                 const float* __restrict__ Wp,
                                                 float* __restrict__ Y,
                                                 float* __restrict__ P,
                                                 const float* __restrict__ a_s,
                                                 const float* __restrict__ a_d,
                                                 float* __restrict__ as_o,
                                                 float* __restrict__ ad_o) {
    __shared__ float Wcs[HD * HD];  // 16KB
    __shared__ float Wps[HD * HD];  // 16KB
    __shared__ float Xs[32 * HD];   // 8KB
    int t = threadIdx.x;
    for (int i = t; i < HD * HD; i += 256) { Wcs[i] = Wc[i]; Wps[i] = Wp[i]; }
    int nb = blockIdx.x * 32;
    for (int i = t; i < 32 * HD; i += 256) {
        int r = i >> 6, c = i & 63;
        int node = nb + r;
        Xs[i] = (node < NN) ? X[(size_t)node * HD + c] : 0.f;
    }
    __syncthreads();
    int cp = t & 31, g = t >> 5;
    float2 c0 = make_float2(0.f, 0.f), c1 = c0, c2 = c0, c3 = c0;
    float2 p0 = c0, p1 = c0, p2 = c0, p3 = c0;
#pragma unroll 4
    for (int k = 0; k < HD; k++) {
        float2 wc = reinterpret_cast<const float2*>(Wcs)[k * 32 + cp];
        float2 wp = reinterpret_cast<const float2*>(Wps)[k * 32 + cp];
        float x0 = Xs[(g * 4 + 0) * HD + k];
        float x1 = Xs[(g * 4 + 1) * HD + k];
        float x2 = Xs[(g * 4 + 2) * HD + k];
        float x3 = Xs[(g * 4 + 3) * HD + k];
        c0.x += x0 * wc.x; c0.y += x0 * wc.y;
        c1.x += x1 * wc.x; c1.y += x1 * wc.y;
        c2.x += x2 * wc.x; c2.y += x2 * wc.y;
        c3.x += x3 * wc.x; c3.y += x3 * wc.y;
        p0.x += x0 * wp.x; p0.y += x0 * wp.y;
        p1.x += x1 * wp.x; p1.y += x1 * wp.y;
        p2.x += x2 * wp.x; p2.y += x2 * wp.y;
        p3.x += x3 * wp.x; p3.y += x3 * wp.y;
    }
    int r0 = nb + g * 4;
    float2* Y2 = reinterpret_cast<float2*>(Y);
    float2* P2 = reinterpret_cast<float2*>(P);
    if (r0 + 0 < NN) { Y2[(size_t)(r0 + 0) * 32 + cp] = c0; P2[(size_t)(r0 + 0) * 32 + cp] = p0; }
    if (r0 + 1 < NN) { Y2[(size_t)(r0 + 1) * 32 + cp] = c1; P2[(size_t)(r0 + 1) * 32 + cp] = p1; }
    if (r0 + 2 < NN) { Y2[(size_t)(r0 + 2) * 32 + cp] = c2; P2[(size_t)(r0 + 2) * 32 + cp] = p2; }
    if (r0 + 3 < NN) { Y2[(size_t)(r0 + 3) * 32 + cp] = c3; P2[(size_t)(r0 + 3) * 32 + cp] = p3; }
    float2 sv = reinterpret_cast<const float2*>(a_s)[cp];
    float2 dv = reinterpret_cast<const float2*>(a_d)[cp];
    float s0 = c0.x * sv.x + c0.y * sv.y;
    float s1 = c1.x * sv.x + c1.y * sv.y;
    float s2 = c2.x * sv.x + c2.y * sv.y;
    float s3 = c3.x * sv.x + c3.y * sv.y;
    float d0 = c0.x * dv.x + c0.y * dv.y;
    float d1 = c1.x * dv.x + c1.y * dv.y;
    float d2 = c2.x * dv.x + c2.y * dv.y;
    float d3 = c3.x * dv.x + c3.y * dv.y;
#pragma unroll
    for (int o = 16; o; o >>= 1) {
        s0 += __shfl_xor_sync(0xffffffffu, s0, o);
        s1 += __shfl_xor_sync(0xffffffffu, s1, o);
        s2 += __shfl_xor_sync(0xffffffffu, s2, o);
        s3 += __shfl_xor_sync(0xffffffffu, s3, o);
        d0 += __shfl_xor_sync(0xffffffffu, d0, o);
        d1 += __shfl_xor_sync(0xffffffffu, d1, o);
        d2 += __shfl_xor_sync(0xffffffffu, d2, o);
        d3 += __shfl_xor_sync(0xffffffffu, d3, o);
    }
    if ((t & 31) == 0) {
        if (r0 + 0 < NN) { as_o[r0 + 0] = s0; ad_o[r0 + 0] = d0; }
        if (r0 + 1 < NN) { as_o[r0 + 1] = s1; ad_o[r0 + 1] = d1; }
        if (r0 + 2 < NN) { as_o[r0 + 2] = s2; ad_o[r0 + 2] = d2; }
        if (r0 + 3 < NN) { as_o[r0 + 3] = s3; ad_o[r0 + 3] = d3; }
    }
}

// ---------------- fused gather-aggregate + softmax + bias/relu/bn(+proj) ------
// One warp per destination node. 4 groups of 8 lanes process 4 edges
// concurrently; within a group, lane q (0..7) covers cols [8q, 8q+7].
template <bool PROJ>
__global__ void __launch_bounds__(256) agg_post(
    const int* __restrict__ roff, const int* __restrict__ cnt,
    const int* __restrict__ esrc, const float* __restrict__ as_,
    const float* __restrict__ ad_, const float* __restrict__ h,
    const float* __restrict__ bias, const float* __restrict__ bg,
    const float* __restrict__ bb, const float* __restrict__ bm,
    const float* __restrict__ bv, const float* __restrict__ proj,
    const float* __restrict__ projb, float* __restrict__ out) {
    int node = (blockIdx.x * blockDim.x + threadIdx.x) >> 5;
    int lane = threadIdx.x & 31;
    if (node >= NN) return;
    int beg = roff[node];
    int m = cnt[node];
    float adn = ad_[node];
    const float4* __restrict__ h4 = reinterpret_cast<const float4*>(h);
    int q = lane & 7, grp = lane >> 3;
    float4 aA = make_float4(0.f, 0.f, 0.f, 0.f);
    float4 aB = make_float4(0.f, 0.f, 0.f, 0.f);
    float denom = 0.f;
    for (int base = 0; base < m; base += 32) {
        int rem = m - base;
        int nn = rem < 32 ? rem : 32;
        int s_l = 0;
        float ex_l = 0.f;
        if (lane < nn) {
            s_l = esrc[beg + base + lane];
            float e = as_[s_l] + adn;
            e = e > 0.f ? e : 0.2f * e;
            ex_l = __expf(e);
        }
        denom += ex_l;
#pragma unroll 2
        for (int j = 0; j < nn; j += 4) {
            int jj = j + grp;
            int s = __shfl_sync(0xffffffffu, s_l, jj & 31);
            float ex = __shfl_sync(0xffffffffu, ex_l, jj & 31);
            if (jj < nn) {
                float4 ha = h4[(size_t)s * 16 + q * 2];
                float4 hb = h4[(size_t)s * 16 + q * 2 + 1];
                aA.x += ex * ha.x; aA.y += ex * ha.y;
                aA.z += ex * ha.z; aA.w += ex * ha.w;
                aB.x += ex * hb.x; aB.y += ex * hb.y;
                aB.z += ex * hb.z; aB.w += ex * hb.w;
            }
        }
    }
    // merge the 4 edge-group partials (same columns, disjoint edge subsets)
#pragma unroll
    for (int o = 8; o <= 16; o <<= 1) {
        aA.x += __shfl_xor_sync(0xffffffffu, aA.x, o);
        aA.y += __shfl_xor_sync(0xffffffffu, aA.y, o);
        aA.z += __shfl_xor_sync(0xffffffffu, aA.z, o);
        aA.w += __shfl_xor_sync(0xffffffffu, aA.w, o);
        aB.x += __shfl_xor_sync(0xffffffffu, aB.x, o);
        aB.y += __shfl_xor_sync(0xffffffffu, aB.y, o);
        aB.z += __shfl_xor_sync(0xffffffffu, aB.z, o);
        aB.w += __shfl_xor_sync(0xffffffffu, aB.w, o);
    }
#pragma unroll
    for (int o = 16; o; o >>= 1) denom += __shfl_xor_sync(0xffffffffu, denom, o);
    if (grp == 0) {
        float inv = 1.f / (denom + 1e-16f);
        const float4* b4p = reinterpret_cast<const float4*>(bias);
        const float4* g4p = reinterpret_cast<const float4*>(bg);
        const float4* be4p = reinterpret_cast<const float4*>(bb);
        const float4* m4p = reinterpret_cast<const float4*>(bm);
        const float4* v4p = reinterpret_cast<const float4*>(bv);
        float4 outA, outB;
        {
            float4 b4 = b4p[q * 2], g4 = g4p[q * 2], be4 = be4p[q * 2];
            float4 m4 = m4p[q * 2], v4 = v4p[q * 2];
            outA.x = (fmaxf(aA.x * inv + b4.x, 0.f) - m4.x) * rsqrtf(v4.x + 1e-5f) * g4.x + be4.x;
            outA.y = (fmaxf(aA.y * inv + b4.y, 0.f) - m4.y) * rsqrtf(v4.y + 1e-5f) * g4.y + be4.y;
            outA.z = (fmaxf(aA.z * inv + b4.z, 0.f) - m4.z) * rsqrtf(v4.z + 1e-5f) * g4.z + be4.z;
            outA.w = (fmaxf(aA.w * inv + b4.w, 0.f) - m4.w) * rsqrtf(v4.w + 1e-5f) * g4.w + be4.w;
        }
        {
            float4 b4 = b4p[q * 2 + 1], g4 = g4p[q * 2 + 1], be4 = be4p[q * 2 + 1];
            float4 m4 = m4p[q * 2 + 1], v4 = v4p[q * 2 + 1];
            outB.x = (fmaxf(aB.x * inv + b4.x, 0.f) - m4.x) * rsqrtf(v4.x + 1e-5f) * g4.x + be4.x;
            outB.y = (fmaxf(aB.y * inv + b4.y, 0.f) - m4.y) * rsqrtf(v4.y + 1e-5f) * g4.y + be4.y;
            outB.z = (fmaxf(aB.z * inv + b4.z, 0.f) - m4.z) * rsqrtf(v4.z + 1e-5f) * g4.z + be4.z;
            outB.w = (fmaxf(aB.w * inv + b4.w, 0.f) - m4.w) * rsqrtf(v4.w + 1e-5f) * g4.w + be4.w;
        }
        if (PROJ) {
            float4 pA = reinterpret_cast<const float4*>(proj)[(size_t)node * 16 + q * 2];
            float4 pB = reinterpret_cast<const float4*>(proj)[(size_t)node * 16 + q * 2 + 1];
            float4 pbA = reinterpret_cast<const float4*>(projb)[q * 2];
            float4 pbB = reinterpret_cast<const float4*>(projb)[q * 2 + 1];
            outA.x += pA.x + pbA.x; outA.y += pA.y + pbA.y;
            outA.z += pA.z + pbA.z; outA.w += pA.w + pbA.w;
            outB.x += pB.x + pbB.x; outB.y += pB.y + pbB.y;
            outB.z += pB.z + pbB.z; outB.w += pB.w + pbB.w;
        }
        reinterpret_cast<float4*>(out)[(size_t)node * 16 + q * 2] = outA;
        reinterpret_cast<float4*>(out)[(size_t)node * 16 + q * 2 + 1] = outB;
    }
}

// ---------------- mean pool ----------------
__global__ void zero_gsum(float* __restrict__ g) {
    if (threadIdx.x < HD) g[threadIdx.x] = 0.f;
}
__global__ void __launch_bounds__(256) pool(const float* __restrict__ xp,
                                            float* __restrict__ gsum) {
    int t = threadIdx.x;
    int c = t & 63;
    int row0 = blockIdx.x * 4 + (t >> 6);
    float acc = 0.f;
    for (int n = row0; n < NN; n += gridDim.x * 4) acc += xp[(size_t)n * HD + c];
    atomicAdd(&gsum[c], acc);
}

// ---------------- head MLP ----------------
__global__ void head(const float* __restrict__ gsum, const float* __restrict__ hW1,
                     const float* __restrict__ hb1, const float* __restrict__ hg,
                     const float* __restrict__ hb, const float* __restrict__ hm,
                     const float* __restrict__ hv, const float* __restrict__ hW2,
                     const float* __restrict__ hb2, float* __restrict__ out) {
    __shared__ float g[HD];
    int t = threadIdx.x;
    if (t < HD) g[t] = gsum[t] * (1.f / NN);
    __syncthreads();
    float r = 0.f;
    if (t < 32) {
        float acc = hb1[t];
#pragma unroll
        for (int k = 0; k < HD; k++) acc += g[k] * hW1[k * 32 + t];
        acc = fmaxf(acc, 0.f);
        acc = (acc - hm[t]) * rsqrtf(hv[t] + 1e-5f) * hg[t] + hb[t];
        r = acc * hW2[t];
#pragma unroll
        for (int o = 16; o; o >>= 1) r += __shfl_xor_sync(0xffffffffu, r, o);
        if (t == 0) out[0] = r + hb2[0];
    }
}

// ---------------- launch ----------------
extern "C" void kernel_launch(void* const* d_in, const int* in_sizes, int n_in,
                              void* d_out, int out_size) {
    (void)in_sizes; (void)n_in; (void)out_size;
    const float* x        = (const float*)d_in[0];
    const int*   ei       = (const int*)d_in[1];
    const float* conv1_W  = (const float*)d_in[2];
    const float* conv1_as = (const float*)d_in[3];
    const float* conv1_ad = (const float*)d_in[4];
    const float* conv1_b  = (const float*)d_in[5];
    const float* convW    = (const float*)d_in[6];
    const float* conv_as  = (const float*)d_in[7];
    const float* conv_ad  = (const float*)d_in[8];
    const float* conv_b   = (const float*)d_in[9];
    const float* bn_g     = (const float*)d_in[10];
    const float* bn_b     = (const float*)d_in[11];
    const float* bn_m     = (const float*)d_in[12];
    const float* bn_v     = (const float*)d_in[13];
    const float* projW    = (const float*)d_in[14];
    const float* projb    = (const float*)d_in[15];
    const float* hW1      = (const float*)d_in[16];
    const float* hb1      = (const float*)d_in[17];
    const float* hbn_g    = (const float*)d_in[18];
    const float* hbn_b    = (const float*)d_in[19];
    const float* hbn_m    = (const float*)d_in[20];
    const float* hbn_v    = (const float*)d_in[21];
    const float* hW2      = (const float*)d_in[22];
    const float* hb2      = (const float*)d_in[23];

    const int* src = ei;
    const int* dst = ei + EE;

    float *h, *x1, *x2, *proj, *as_, *ad_, *gsum;
    int *cnt, *roff, *fill, *bsum, *esrc;
    cudaGetSymbolAddress((void**)&h, d_h);
    cudaGetSymbolAddress((void**)&x1, d_x1);
    cudaGetSymbolAddress((void**)&x2, d_x2);
    cudaGetSymbolAddress((void**)&proj, d_proj);
    cudaGetSymbolAddress((void**)&as_, d_as);
    cudaGetSymbolAddress((void**)&ad_, d_ad);
    cudaGetSymbolAddress((void**)&gsum, d_gsum);
    cudaGetSymbolAddress((void**)&cnt, d_cnt);
    cudaGetSymbolAddress((void**)&roff, d_roff);
    cudaGetSymbolAddress((void**)&fill, d_fill);
    cudaGetSymbolAddress((void**)&bsum, d_bsum);
    cudaGetSymbolAddress((void**)&esrc, d_esrc);

    const int G1 = (NN + 15) / 16;             // gemm1 blocks (16 rows)
    const int GD = (NN + 31) / 32;             // gemm_dual blocks (32 rows)
    const int AB = (NN * 32 + 255) / 256;      // warp-per-node blocks
    const int NB = (NN + 255) / 256;           // node-sized blocks
    const int MB = (TOTE + 255) / 256;         // edge-sized blocks

    // ---- CSR build (per launch; edge_index constant) ----
    zero_cf<<<NB, 256>>>(cnt, fill);
    hist<<<MB, 256>>>(dst, cnt);
    scan1<<<NB_SCAN, 256>>>(cnt, roff, bsum);
    scan2<<<1, 256>>>(bsum);
    scan3<<<NB_SCAN, 256>>>(roff, bsum);
    scatter<<<MB, 256>>>(src, dst, roff, fill, esrc);

    // ---- layer 1 ----
    gemm1<<<G1, 256>>>(x, conv1_W, h, conv1_as, conv1_ad, as_, ad_);
    agg_post<false><<<AB, 256>>>(roff, cnt, esrc, as_, ad_, h, conv1_b, bn_g,
                                 bn_b, bn_m, bn_v, nullptr, nullptr, x1);

    float* xp = x1;
    float* xn = x2;
    for (int l = 0; l < 4; l++) {
        gemm_dual<<<GD, 256>>>(xp, convW + l * HD * HD, projW + l * HD * HD, h,
                               proj, conv_as + l * HD, conv_ad + l * HD, as_,
                               ad_);
        agg_post<true><<<AB, 256>>>(roff, cnt, esrc, as_, ad_, h,
                                    conv_b + l * HD, bn_g + (l + 1) * HD,
                                    bn_b + (l + 1) * HD, bn_m + (l + 1) * HD,
                                    bn_v + (l + 1) * HD, proj, projb + l * HD,
                                    xn);
        float* tmp = xp; xp = xn; xn = tmp;
    }

    zero_gsum<<<1, 64>>>(gsum);
    pool<<<256, 256>>>(xp, gsum);
    head<<<1, 64>>>(gsum, hW1, hb1, hbn_g, hbn_b, hbn_m, hbn_v, hW2, hb2,
                    (float*)d_out);
}

// round 11
// speedup vs baseline: 1.3042x; 1.1346x over previous
#include <cuda_runtime.h>

#define NN 50000
#define EE 800000
#define IND 128
#define HD 64
#define TOTE (EE + NN)
#define NB_SCAN 196   // ceil(NN/256)

// ---------------- scratch (static device memory; no allocations) ----------------
__device__ __align__(256) float d_h[NN * HD];
__device__ __align__(256) float d_x1[NN * HD];
__device__ __align__(256) float d_x2[NN * HD];
__device__ __align__(256) float d_proj[NN * HD];
__device__ __align__(256) float d_as[NN];
__device__ __align__(256) float d_ad[NN];
__device__ __align__(256) float d_gsum[HD];
__device__ __align__(256) int   d_cnt[NN];
__device__ __align__(256) int   d_roff[NN];
__device__ __align__(256) int   d_fill[NN];
__device__ __align__(256) int   d_bsum[NB_SCAN];
__device__ __align__(256) int   d_esrc[TOTE];

// ---------------- CSR build ----------------
__global__ void __launch_bounds__(256) zero_cf(int* __restrict__ cnt,
                                               int* __restrict__ fill) {
    int i = blockIdx.x * blockDim.x + threadIdx.x;
    if (i < NN) { cnt[i] = 0; fill[i] = 0; }
}

__global__ void __launch_bounds__(256) hist(const int* __restrict__ dst,
                                            int* __restrict__ cnt) {
    int i = blockIdx.x * blockDim.x + threadIdx.x;
    if (i >= TOTE) return;
    int d = (i < EE) ? dst[i] : (i - EE);
    atomicAdd(&cnt[d], 1);
}

__global__ void __launch_bounds__(256) scan1(const int* __restrict__ cnt,
                                             int* __restrict__ roff,
                                             int* __restrict__ bsum) {
    __shared__ int sh[256];
    int t = threadIdx.x;
    int i = blockIdx.x * 256 + t;
    int v = (i < NN) ? cnt[i] : 0;
    sh[t] = v;
    __syncthreads();
#pragma unroll
    for (int o = 1; o < 256; o <<= 1) {
        int u = (t >= o) ? sh[t - o] : 0;
        __syncthreads();
        sh[t] += u;
        __syncthreads();
    }
    if (i < NN) roff[i] = sh[t] - v;           // exclusive
    if (t == 255) bsum[blockIdx.x] = sh[255];  // block total
}

__global__ void __launch_bounds__(256) scan2(int* __restrict__ bsum) {
    __shared__ int sh[256];
    int t = threadIdx.x;
    int v = (t < NB_SCAN) ? bsum[t] : 0;
    sh[t] = v;
    __syncthreads();
#pragma unroll
    for (int o = 1; o < 256; o <<= 1) {
        int u = (t >= o) ? sh[t - o] : 0;
        __syncthreads();
        sh[t] += u;
        __syncthreads();
    }
    if (t < NB_SCAN) bsum[t] = sh[t] - v;      // exclusive over blocks
}

__global__ void __launch_bounds__(256) scan3(int* __restrict__ roff,
                                             const int* __restrict__ bsum) {
    int i = blockIdx.x * blockDim.x + threadIdx.x;
    if (i < NN) roff[i] += bsum[i >> 8];
}

__global__ void __launch_bounds__(256) scatter(const int* __restrict__ src,
                                               const int* __restrict__ dst,
                                               const int* __restrict__ roff,
                                               int* __restrict__ fill,
                                               int* __restrict__ esrc) {
    int i = blockIdx.x * blockDim.x + threadIdx.x;
    if (i >= TOTE) return;
    int s, d;
    if (i < EE) { s = src[i]; d = dst[i]; } else { s = d = i - EE; }
    int pos = roff[d] + atomicAdd(&fill[d], 1);
    esrc[pos] = s;
}

// ---------------- layer-1 GEMM (K=128) + fused scores ----------------
// 256 threads: cp = t&31 (col pair), g = t>>5 (8 groups x 4 rows) -> 32 rows/blk
__global__ void __launch_bounds__(256) gemm1(const float* __restrict__ X,
                                             const float* __restrict__ W,
                                             float* __restrict__ Y,
                                             const float* __restrict__ a_s,
                                             const float* __restrict__ a_d,
                                             float* __restrict__ as_o,
                                             float* __restrict__ ad_o) {
    __shared__ float Ws[IND * HD];   // 32KB
    __shared__ float Xs[32 * IND];   // 16KB
    int t = threadIdx.x;
    for (int i = t; i < IND * HD; i += 256) Ws[i] = W[i];
    int nb = blockIdx.x * 32;
    for (int i = t; i < 32 * IND; i += 256) {
        int r = i >> 7, c = i & 127;
        int node = nb + r;
        Xs[i] = (node < NN) ? X[(size_t)node * IND + c] : 0.f;
    }
    __syncthreads();
    int cp = t & 31, g = t >> 5;
    float2 a0 = make_float2(0.f, 0.f), a1 = a0, a2 = a0, a3 = a0;
#pragma unroll 8
    for (int k = 0; k < IND; k++) {
        float2 w = reinterpret_cast<const float2*>(Ws)[k * 32 + cp];
        float x0 = Xs[(g * 4 + 0) * IND + k];
        float x1 = Xs[(g * 4 + 1) * IND + k];
        float x2 = Xs[(g * 4 + 2) * IND + k];
        float x3 = Xs[(g * 4 + 3) * IND + k];
        a0.x += x0 * w.x; a0.y += x0 * w.y;
        a1.x += x1 * w.x; a1.y += x1 * w.y;
        a2.x += x2 * w.x; a2.y += x2 * w.y;
        a3.x += x3 * w.x; a3.y += x3 * w.y;
    }
    int r0 = nb + g * 4;
    float2* Y2 = reinterpret_cast<float2*>(Y);
    if (r0 + 0 < NN) Y2[(size_t)(r0 + 0) * 32 + cp] = a0;
    if (r0 + 1 < NN) Y2[(size_t)(r0 + 1) * 32 + cp] = a1;
    if (r0 + 2 < NN) Y2[(size_t)(r0 + 2) * 32 + cp] = a2;
    if (r0 + 3 < NN) Y2[(size_t)(r0 + 3) * 32 + cp] = a3;
    float2 sv = reinterpret_cast<const float2*>(a_s)[cp];
    float2 dv = reinterpret_cast<const float2*>(a_d)[cp];
    float s0 = a0.x * sv.x + a0.y * sv.y;
    float s1 = a1.x * sv.x + a1.y * sv.y;
    float s2 = a2.x * sv.x + a2.y * sv.y;
    float s3 = a3.x * sv.x + a3.y * sv.y;
    float d0 = a0.x * dv.x + a0.y * dv.y;
    float d1 = a1.x * dv.x + a1.y * dv.y;
    float d2 = a2.x * dv.x + a2.y * dv.y;
    float d3 = a3.x * dv.x + a3.y * dv.y;
#pragma unroll
    for (int o = 16; o; o >>= 1) {
        s0 += __shfl_xor_sync(0xffffffffu, s0, o);
        s1 += __shfl_xor_sync(0xffffffffu, s1, o);
        s2 += __shfl_xor_sync(0xffffffffu, s2, o);
        s3 += __shfl_xor_sync(0xffffffffu, s3, o);
        d0 += __shfl_xor_sync(0xffffffffu, d0, o);
        d1 += __shfl_xor_sync(0xffffffffu, d1, o);
        d2 += __shfl_xor_sync(0xffffffffu, d2, o);
        d3 += __shfl_xor_sync(0xffffffffu, d3, o);
    }
    if ((t & 31) == 0) {
        if (r0 + 0 < NN) { as_o[r0 + 0] = s0; ad_o[r0 + 0] = d0; }
        if (r0 + 1 < NN) { as_o[r0 + 1] = s1; ad_o[r0 + 1] = d1; }
        if (r0 + 2 < NN) { as_o[r0 + 2] = s2; ad_o[r0 + 2] = d2; }
        if (r0 + 3 < NN) { as_o[r0 + 3] = s3; ad_o[r0 + 3] = d3; }
    }
}

// ---------------- dual GEMM (K=64): Y = X@Wc (+scores), P = X@Wp ----------
// 256 threads: cp = t&31 (col pair), g = t>>5 (8 groups x 4 rows) -> 32 rows/blk
__global__ void __launch_bounds__(256) gemm_dual(const float* __restrict__ X,
                                                 const float* __restrict__ Wc,
                                                 const float* __restrict__ Wp,
                                                 float* __restrict__ Y,
                                                 float* __restrict__ P,
                                                 const float* __restrict__ a_s,
                                                 const float* __restrict__ a_d,
                                                 float* __restrict__ as_o,
                                                 float* __restrict__ ad_o) {
    __shared__ float Wcs[HD * HD];  // 16KB
    __shared__ float Wps[HD * HD];  // 16KB
    __shared__ float Xs[32 * HD];   // 8KB
    int t = threadIdx.x;
    for (int i = t; i < HD * HD; i += 256) { Wcs[i] = Wc[i]; Wps[i] = Wp[i]; }
    int nb = blockIdx.x * 32;
    for (int i = t; i < 32 * HD; i += 256) {
        int r = i >> 6, c = i & 63;
        int node = nb + r;
        Xs[i] = (node < NN) ? X[(size_t)node * HD + c] : 0.f;
    }
    __syncthreads();
    int cp = t & 31, g = t >> 5;
    float2 c0 = make_float2(0.f, 0.f), c1 = c0, c2 = c0, c3 = c0;
    float2 p0 = c0, p1 = c0, p2 = c0, p3 = c0;
#pragma unroll 4
    for (int k = 0; k < HD; k++) {
        float2 wc = reinterpret_cast<const float2*>(Wcs)[k * 32 + cp];
        float2 wp = reinterpret_cast<const float2*>(Wps)[k * 32 + cp];
        float x0 = Xs[(g * 4 + 0) * HD + k];
        float x1 = Xs[(g * 4 + 1) * HD + k];
        float x2 = Xs[(g * 4 + 2) * HD + k];
        float x3 = Xs[(g * 4 + 3) * HD + k];
        c0.x += x0 * wc.x; c0.y += x0 * wc.y;
        c1.x += x1 * wc.x; c1.y += x1 * wc.y;
        c2.x += x2 * wc.x; c2.y += x2 * wc.y;
        c3.x += x3 * wc.x; c3.y += x3 * wc.y;
        p0.x += x0 * wp.x; p0.y += x0 * wp.y;
        p1.x += x1 * wp.x; p1.y += x1 * wp.y;
        p2.x += x2 * wp.x; p2.y += x2 * wp.y;
        p3.x += x3 * wp.x; p3.y += x3 * wp.y;
    }
    int r0 = nb + g * 4;
    float2* Y2 = reinterpret_cast<float2*>(Y);
    float2* P2 = reinterpret_cast<float2*>(P);
    if (r0 + 0 < NN) { Y2[(size_t)(r0 + 0) * 32 + cp] = c0; P2[(size_t)(r0 + 0) * 32 + cp] = p0; }
    if (r0 + 1 < NN) { Y2[(size_t)(r0 + 1) * 32 + cp] = c1; P2[(size_t)(r0 + 1) * 32 + cp] = p1; }
    if (r0 + 2 < NN) { Y2[(size_t)(r0 + 2) * 32 + cp] = c2; P2[(size_t)(r0 + 2) * 32 + cp] = p2; }
    if (r0 + 3 < NN) { Y2[(size_t)(r0 + 3) * 32 + cp] = c3; P2[(size_t)(r0 + 3) * 32 + cp] = p3; }
    float2 sv = reinterpret_cast<const float2*>(a_s)[cp];
    float2 dv = reinterpret_cast<const float2*>(a_d)[cp];
    float s0 = c0.x * sv.x + c0.y * sv.y;
    float s1 = c1.x * sv.x + c1.y * sv.y;
    float s2 = c2.x * sv.x + c2.y * sv.y;
    float s3 = c3.x * sv.x + c3.y * sv.y;
    float d0 = c0.x * dv.x + c0.y * dv.y;
    float d1 = c1.x * dv.x + c1.y * dv.y;
    float d2 = c2.x * dv.x + c2.y * dv.y;
    float d3 = c3.x * dv.x + c3.y * dv.y;
#pragma unroll
    for (int o = 16; o; o >>= 1) {
        s0 += __shfl_xor_sync(0xffffffffu, s0, o);
        s1 += __shfl_xor_sync(0xffffffffu, s1, o);
        s2 += __shfl_xor_sync(0xffffffffu, s2, o);
        s3 += __shfl_xor_sync(0xffffffffu, s3, o);
        d0 += __shfl_xor_sync(0xffffffffu, d0, o);
        d1 += __shfl_xor_sync(0xffffffffu, d1, o);
        d2 += __shfl_xor_sync(0xffffffffu, d2, o);
        d3 += __shfl_xor_sync(0xffffffffu, d3, o);
    }
    if ((t & 31) == 0) {
        if (r0 + 0 < NN) { as_o[r0 + 0] = s0; ad_o[r0 + 0] = d0; }
        if (r0 + 1 < NN) { as_o[r0 + 1] = s1; ad_o[r0 + 1] = d1; }
        if (r0 + 2 < NN) { as_o[r0 + 2] = s2; ad_o[r0 + 2] = d2; }
        if (r0 + 3 < NN) { as_o[r0 + 3] = s3; ad_o[r0 + 3] = d3; }
    }
}

// ---------------- fused gather-aggregate + softmax + bias/relu/bn(+proj) ------
// One warp per destination node. Half-warps process 2 edges concurrently;
// within a half, lane q (0..15) covers cols [4q, 4q+3] (float4).
template <bool PROJ>
__global__ void __launch_bounds__(256) agg_post(
    const int* __restrict__ roff, const int* __restrict__ cnt,
    const int* __restrict__ esrc, const float* __restrict__ as_,
    const float* __restrict__ ad_, const float* __restrict__ h,
    const float* __restrict__ bias, const float* __restrict__ bg,
    const float* __restrict__ bb, const float* __restrict__ bm,
    const float* __restrict__ bv, const float* __restrict__ proj,
    const float* __restrict__ projb, float* __restrict__ out) {
    int node = (blockIdx.x * blockDim.x + threadIdx.x) >> 5;
    int lane = threadIdx.x & 31;
    if (node >= NN) return;
    int beg = roff[node];
    int m = cnt[node];
    float adn = ad_[node];
    const float4* __restrict__ h4 = reinterpret_cast<const float4*>(h);
    int q = lane & 15, half = lane >> 4;
    float ax = 0.f, ay = 0.f, az = 0.f, aw = 0.f, denom = 0.f;
    for (int base = 0; base < m; base += 32) {
        int rem = m - base;
        int nn = rem < 32 ? rem : 32;
        int s_l = 0;
        float ex_l = 0.f;
        if (lane < nn) {
            s_l = esrc[beg + base + lane];
            float e = as_[s_l] + adn;
            e = e > 0.f ? e : 0.2f * e;
            ex_l = __expf(e);
        }
        denom += ex_l;
#pragma unroll 2
        for (int j = 0; j < nn; j += 2) {
            int jj = j + half;
            int s = __shfl_sync(0xffffffffu, s_l, jj & 31);
            float ex = __shfl_sync(0xffffffffu, ex_l, jj & 31);
            if (jj < nn) {
                float4 hv = h4[(size_t)s * 16 + q];
                ax += ex * hv.x;
                ay += ex * hv.y;
                az += ex * hv.z;
                aw += ex * hv.w;
            }
        }
    }
    // merge the two edge-halves (same columns, disjoint edge subsets)
    ax += __shfl_xor_sync(0xffffffffu, ax, 16);
    ay += __shfl_xor_sync(0xffffffffu, ay, 16);
    az += __shfl_xor_sync(0xffffffffu, az, 16);
    aw += __shfl_xor_sync(0xffffffffu, aw, 16);
#pragma unroll
    for (int o = 16; o; o >>= 1) denom += __shfl_xor_sync(0xffffffffu, denom, o);
    if (half == 0) {
        float inv = 1.f / (denom + 1e-16f);
        float4 b4 = reinterpret_cast<const float4*>(bias)[q];
        float4 g4 = reinterpret_cast<const float4*>(bg)[q];
        float4 be4 = reinterpret_cast<const float4*>(bb)[q];
        float4 m4 = reinterpret_cast<const float4*>(bm)[q];
        float4 v4 = reinterpret_cast<const float4*>(bv)[q];
        float vx = fmaxf(ax * inv + b4.x, 0.f);
        float vy = fmaxf(ay * inv + b4.y, 0.f);
        float vz = fmaxf(az * inv + b4.z, 0.f);
        float vw = fmaxf(aw * inv + b4.w, 0.f);
        vx = (vx - m4.x) * rsqrtf(v4.x + 1e-5f) * g4.x + be4.x;
        vy = (vy - m4.y) * rsqrtf(v4.y + 1e-5f) * g4.y + be4.y;
        vz = (vz - m4.z) * rsqrtf(v4.z + 1e-5f) * g4.z + be4.z;
        vw = (vw - m4.w) * rsqrtf(v4.w + 1e-5f) * g4.w + be4.w;
        if (PROJ) {
            float4 p4 = reinterpret_cast<const float4*>(proj)[(size_t)node * 16 + q];
            float4 pb4 = reinterpret_cast<const float4*>(projb)[q];
            vx += p4.x + pb4.x;
            vy += p4.y + pb4.y;
            vz += p4.z + pb4.z;
            vw += p4.w + pb4.w;
        }
        reinterpret_cast<float4*>(out)[(size_t)node * 16 + q] =
            make_float4(vx, vy, vz, vw);
    }
}

// ---------------- mean pool ----------------
__global__ void zero_gsum(float* __restrict__ g) {
    if (threadIdx.x < HD) g[threadIdx.x] = 0.f;
}
__global__ void __launch_bounds__(256) pool(const float* __restrict__ xp,
                                            float* __restrict__ gsum) {
    int t = threadIdx.x;
    int c = t & 63;
    int row0 = blockIdx.x * 4 + (t >> 6);
    float acc = 0.f;
    for (int n = row0; n < NN; n += gridDim.x * 4) acc += xp[(size_t)n * HD + c];
    atomicAdd(&gsum[c], acc);
}

// ---------------- head MLP ----------------
__global__ void head(const float* __restrict__ gsum, const float* __restrict__ hW1,
                     const float* __restrict__ hb1, const float* __restrict__ hg,
                     const float* __restrict__ hb, const float* __restrict__ hm,
                     const float* __restrict__ hv, const float* __restrict__ hW2,
                     const float* __restrict__ hb2, float* __restrict__ out) {
    __shared__ float g[HD];
    int t = threadIdx.x;
    if (t < HD) g[t] = gsum[t] * (1.f / NN);
    __syncthreads();
    float r = 0.f;
    if (t < 32) {
        float acc = hb1[t];
#pragma unroll
        for (int k = 0; k < HD; k++) acc += g[k] * hW1[k * 32 + t];
        acc = fmaxf(acc, 0.f);
        acc = (acc - hm[t]) * rsqrtf(hv[t] + 1e-5f) * hg[t] + hb[t];
        r = acc * hW2[t];
#pragma unroll
        for (int o = 16; o; o >>= 1) r += __shfl_xor_sync(0xffffffffu, r, o);
        if (t == 0) out[0] = r + hb2[0];
    }
}

// ---------------- launch ----------------
extern "C" void kernel_launch(void* const* d_in, const int* in_sizes, int n_in,
                              void* d_out, int out_size) {
    (void)in_sizes; (void)n_in; (void)out_size;
    const float* x        = (const float*)d_in[0];
    const int*   ei       = (const int*)d_in[1];
    const float* conv1_W  = (const float*)d_in[2];
    const float* conv1_as = (const float*)d_in[3];
    const float* conv1_ad = (const float*)d_in[4];
    const float* conv1_b  = (const float*)d_in[5];
    const float* convW    = (const float*)d_in[6];
    const float* conv_as  = (const float*)d_in[7];
    const float* conv_ad  = (const float*)d_in[8];
    const float* conv_b   = (const float*)d_in[9];
    const float* bn_g     = (const float*)d_in[10];
    const float* bn_b     = (const float*)d_in[11];
    const float* bn_m     = (const float*)d_in[12];
    const float* bn_v     = (const float*)d_in[13];
    const float* projW    = (const float*)d_in[14];
    const float* projb    = (const float*)d_in[15];
    const float* hW1      = (const float*)d_in[16];
    const float* hb1      = (const float*)d_in[17];
    const float* hbn_g    = (const float*)d_in[18];
    const float* hbn_b    = (const float*)d_in[19];
    const float* hbn_m    = (const float*)d_in[20];
    const float* hbn_v    = (const float*)d_in[21];
    const float* hW2      = (const float*)d_in[22];
    const float* hb2      = (const float*)d_in[23];

    const int* src = ei;
    const int* dst = ei + EE;

    float *h, *x1, *x2, *proj, *as_, *ad_, *gsum;
    int *cnt, *roff, *fill, *bsum, *esrc;
    cudaGetSymbolAddress((void**)&h, d_h);
    cudaGetSymbolAddress((void**)&x1, d_x1);
    cudaGetSymbolAddress((void**)&x2, d_x2);
    cudaGetSymbolAddress((void**)&proj, d_proj);
    cudaGetSymbolAddress((void**)&as_, d_as);
    cudaGetSymbolAddress((void**)&ad_, d_ad);
    cudaGetSymbolAddress((void**)&gsum, d_gsum);
    cudaGetSymbolAddress((void**)&cnt, d_cnt);
    cudaGetSymbolAddress((void**)&roff, d_roff);
    cudaGetSymbolAddress((void**)&fill, d_fill);
    cudaGetSymbolAddress((void**)&bsum, d_bsum);
    cudaGetSymbolAddress((void**)&esrc, d_esrc);

    const int G1 = (NN + 31) / 32;             // gemm1 blocks (32 rows)
    const int GD = (NN + 31) / 32;             // gemm_dual blocks (32 rows)
    const int AB = (NN * 32 + 255) / 256;      // warp-per-node blocks
    const int NB = (NN + 255) / 256;           // node-sized blocks
    const int MB = (TOTE + 255) / 256;         // edge-sized blocks

    // ---- CSR build (per launch; edge_index constant) ----
    zero_cf<<<NB, 256>>>(cnt, fill);
    hist<<<MB, 256>>>(dst, cnt);
    scan1<<<NB_SCAN, 256>>>(cnt, roff, bsum);
    scan2<<<1, 256>>>(bsum);
    scan3<<<NB_SCAN, 256>>>(roff, bsum);
    scatter<<<MB, 256>>>(src, dst, roff, fill, esrc);

    // ---- layer 1 ----
    gemm1<<<G1, 256>>>(x, conv1_W, h, conv1_as, conv1_ad, as_, ad_);
    agg_post<false><<<AB, 256>>>(roff, cnt, esrc, as_, ad_, h, conv1_b, bn_g,
                                 bn_b, bn_m, bn_v, nullptr, nullptr, x1);

    float* xp = x1;
    float* xn = x2;
    for (int l = 0; l < 4; l++) {
        gemm_dual<<<GD, 256>>>(xp, convW + l * HD * HD, projW + l * HD * HD, h,
                               proj, conv_as + l * HD, conv_ad + l * HD, as_,
                               ad_);
        agg_post<true><<<AB, 256>>>(roff, cnt, esrc, as_, ad_, h,
                                    conv_b + l * HD, bn_g + (l + 1) * HD,
                                    bn_b + (l + 1) * HD, bn_m + (l + 1) * HD,
                                    bn_v + (l + 1) * HD, proj, projb + l * HD,
                                    xn);
        float* tmp = xp; xp = xn; xn = tmp;
    }

    zero_gsum<<<1, 64>>>(gsum);
    pool<<<256, 256>>>(xp, gsum);
    head<<<1, 64>>>(gsum, hW1, hb1, hbn_g, hbn_b, hbn_m, hbn_v, hW2, hb2,
                    (float*)d_out);
}

// round 12
// speedup vs baseline: 1.4450x; 1.1080x over previous
#include <cuda_runtime.h>

#define NN 50000
#define EE 800000
#define IND 128
#define HD 64
#define TOTE (EE + NN)
#define NB_SCAN 196   // ceil(NN/256)

// ---------------- scratch (static device memory; no allocations) ----------------
__device__ __align__(256) float d_h[NN * HD];
__device__ __align__(256) float d_x1[NN * HD];
__device__ __align__(256) float d_x2[NN * HD];
__device__ __align__(256) float d_proj[NN * HD];
__device__ __align__(256) float d_as[NN];
__device__ __align__(256) float d_ad[NN];
__device__ __align__(256) float d_gsum[HD];
__device__ __align__(256) int   d_cnt[NN];
__device__ __align__(256) int   d_roff[NN];
__device__ __align__(256) int   d_fill[NN];
__device__ __align__(256) int   d_bsum[NB_SCAN];
__device__ __align__(256) int   d_esrc[TOTE];
// W fragments: [mat(8)][ks(8)][nt(8)][lane(32)] x float4(bh0,bh1,bl0,bl1)
__device__ __align__(256) float d_wfrag[8 * 8 * 8 * 32 * 4];

// ---------------- tf32 helpers ----------------
__device__ __forceinline__ unsigned cvt_tf32(float x) {
    unsigned r;
    asm("cvt.rna.tf32.f32 %0, %1;" : "=r"(r) : "f"(x));
    return r;
}
__device__ __forceinline__ void mma_tf32(float* c, unsigned a0, unsigned a1,
                                         unsigned a2, unsigned a3, unsigned b0,
                                         unsigned b1) {
    asm("mma.sync.aligned.m16n8k8.row.col.f32.tf32.tf32.f32 "
        "{%0,%1,%2,%3},{%4,%5,%6,%7},{%8,%9},{%0,%1,%2,%3};"
        : "+f"(c[0]), "+f"(c[1]), "+f"(c[2]), "+f"(c[3])
        : "r"(a0), "r"(a1), "r"(a2), "r"(a3), "r"(b0), "r"(b1));
}

// ---------------- CSR build ----------------
__global__ void __launch_bounds__(256) zero_cf(int* __restrict__ cnt,
                                               int* __restrict__ fill) {
    int i = blockIdx.x * blockDim.x + threadIdx.x;
    if (i < NN) { cnt[i] = 0; fill[i] = 0; }
}

__global__ void __launch_bounds__(256) hist(const int* __restrict__ dst,
                                            int* __restrict__ cnt) {
    int i = blockIdx.x * blockDim.x + threadIdx.x;
    if (i >= TOTE) return;
    int d = (i < EE) ? dst[i] : (i - EE);
    atomicAdd(&cnt[d], 1);
}

__global__ void __launch_bounds__(256) scan1(const int* __restrict__ cnt,
                                             int* __restrict__ roff,
                                             int* __restrict__ bsum) {
    __shared__ int sh[256];
    int t = threadIdx.x;
    int i = blockIdx.x * 256 + t;
    int v = (i < NN) ? cnt[i] : 0;
    sh[t] = v;
    __syncthreads();
#pragma unroll
    for (int o = 1; o < 256; o <<= 1) {
        int u = (t >= o) ? sh[t - o] : 0;
        __syncthreads();
        sh[t] += u;
        __syncthreads();
    }
    if (i < NN) roff[i] = sh[t] - v;           // exclusive
    if (t == 255) bsum[blockIdx.x] = sh[255];  // block total
}

__global__ void __launch_bounds__(256) scan2(int* __restrict__ bsum) {
    __shared__ int sh[256];
    int t = threadIdx.x;
    int v = (t < NB_SCAN) ? bsum[t] : 0;
    sh[t] = v;
    __syncthreads();
#pragma unroll
    for (int o = 1; o < 256; o <<= 1) {
        int u = (t >= o) ? sh[t - o] : 0;
        __syncthreads();
        sh[t] += u;
        __syncthreads();
    }
    if (t < NB_SCAN) bsum[t] = sh[t] - v;      // exclusive over blocks
}

__global__ void __launch_bounds__(256) scan3(int* __restrict__ roff,
                                             const int* __restrict__ bsum) {
    int i = blockIdx.x * blockDim.x + threadIdx.x;
    if (i < NN) roff[i] += bsum[i >> 8];
}

__global__ void __launch_bounds__(256) scatter(const int* __restrict__ src,
                                               const int* __restrict__ dst,
                                               const int* __restrict__ roff,
                                               int* __restrict__ fill,
                                               int* __restrict__ esrc) {
    int i = blockIdx.x * blockDim.x + threadIdx.x;
    if (i >= TOTE) return;
    int s, d;
    if (i < EE) { s = src[i]; d = dst[i]; } else { s = d = i - EE; }
    int pos = roff[d] + atomicAdd(&fill[d], 1);
    esrc[pos] = s;
}

// ---------------- prep W fragments (hi/lo tf32, coalesced layout) ----------
// One thread per (mat, ks, nt, lane); writes float4 (bh0, bh1, bl0, bl1).
__global__ void __launch_bounds__(256) prep_w(const float* __restrict__ convW,
                                              const float* __restrict__ projW,
                                              float* __restrict__ wf) {
    int i = blockIdx.x * 256 + threadIdx.x;  // 0 .. 8*8*8*32-1 = 16383
    if (i >= 8 * 8 * 8 * 32) return;
    int lane = i & 31;
    int nt = (i >> 5) & 7;
    int ks = (i >> 8) & 7;
    int mat = i >> 11;
    int tid = lane & 3, gid = lane >> 2;
    const float* W = (mat < 4) ? convW + mat * HD * HD : projW + (mat - 4) * HD * HD;
    float v0 = W[(ks * 8 + tid) * HD + nt * 8 + gid];
    float v1 = W[(ks * 8 + tid + 4) * HD + nt * 8 + gid];
    unsigned h0 = cvt_tf32(v0), h1 = cvt_tf32(v1);
    unsigned l0 = cvt_tf32(v0 - __uint_as_float(h0));
    unsigned l1 = cvt_tf32(v1 - __uint_as_float(h1));
    reinterpret_cast<float4*>(wf)[i] =
        make_float4(__uint_as_float(h0), __uint_as_float(h1),
                    __uint_as_float(l0), __uint_as_float(l1));
}

// ---------------- layer-1 GEMM (K=128) + fused scores (R7 form) ----------
// 256 threads: cp = t&31 (col pair), g = t>>5 (8 groups x 2 rows) -> 16 rows/blk
__global__ void __launch_bounds__(256) gemm1(const float* __restrict__ X,
                                             const float* __restrict__ W,
                                             float* __restrict__ Y,
                                             const float* __restrict__ a_s,
                                             const float* __restrict__ a_d,
                                             float* __restrict__ as_o,
                                             float* __restrict__ ad_o) {
    __shared__ float Ws[IND * HD];   // 32KB
    __shared__ float Xs[16 * IND];   // 8KB
    int t = threadIdx.x;
    for (int i = t; i < IND * HD; i += 256) Ws[i] = W[i];
    int nb = blockIdx.x * 16;
    for (int i = t; i < 16 * IND; i += 256) {
        int r = i >> 7, c = i & 127;
        int node = nb + r;
        Xs[i] = (node < NN) ? X[(size_t)node * IND + c] : 0.f;
    }
    __syncthreads();
    int cp = t & 31, g = t >> 5;
    float2 a0 = make_float2(0.f, 0.f), a1 = make_float2(0.f, 0.f);
#pragma unroll 8
    for (int k = 0; k < IND; k++) {
        float2 w = reinterpret_cast<const float2*>(Ws)[k * 32 + cp];
        float x0 = Xs[(g * 2 + 0) * IND + k];
        float x1 = Xs[(g * 2 + 1) * IND + k];
        a0.x += x0 * w.x; a0.y += x0 * w.y;
        a1.x += x1 * w.x; a1.y += x1 * w.y;
    }
    int r0 = nb + g * 2;
    if (r0 < NN)
        reinterpret_cast<float2*>(Y)[(size_t)r0 * 32 + cp] = a0;
    if (r0 + 1 < NN)
        reinterpret_cast<float2*>(Y)[(size_t)(r0 + 1) * 32 + cp] = a1;
    float2 sv = reinterpret_cast<const float2*>(a_s)[cp];
    float2 dv = reinterpret_cast<const float2*>(a_d)[cp];
    float s0 = a0.x * sv.x + a0.y * sv.y;
    float s1 = a1.x * sv.x + a1.y * sv.y;
    float d0 = a0.x * dv.x + a0.y * dv.y;
    float d1 = a1.x * dv.x + a1.y * dv.y;
#pragma unroll
    for (int o = 16; o; o >>= 1) {
        s0 += __shfl_xor_sync(0xffffffffu, s0, o);
        s1 += __shfl_xor_sync(0xffffffffu, s1, o);
        d0 += __shfl_xor_sync(0xffffffffu, d0, o);
        d1 += __shfl_xor_sync(0xffffffffu, d1, o);
    }
    if ((t & 31) == 0) {
        if (r0 < NN) { as_o[r0] = s0; ad_o[r0] = d0; }
        if (r0 + 1 < NN) { as_o[r0 + 1] = s1; ad_o[r0 + 1] = d1; }
    }
}

// ---------------- dual GEMM via tf32 mma v2 ----------------
// 64 rows/block, 256 threads. Warps 0-3: conv (+scores); warps 4-7: proj.
// Each warp: 16 rows x 64 cols. B frags coalesced [ks][nt][lane]float4.
__global__ void __launch_bounds__(256) gemm_dual_mma(
    const float* __restrict__ X, const float* __restrict__ wf_c,
    const float* __restrict__ wf_p, float* __restrict__ Y,
    float* __restrict__ P, const float* __restrict__ a_s,
    const float* __restrict__ a_d, float* __restrict__ as_o,
    float* __restrict__ ad_o) {
    __shared__ float Xs[64 * 68];    // padded stride 68, ~17.4KB
    __shared__ float as_sh[HD], ad_sh[HD];
    int t = threadIdx.x;
    int nb = blockIdx.x * 64;
    for (int i = t; i < 64 * 64; i += 256) {
        int r = i >> 6, c = i & 63;
        int node = nb + r;
        Xs[r * 68 + c] = (node < NN) ? X[(size_t)node * HD + c] : 0.f;
    }
    if (t < HD) { as_sh[t] = a_s[t]; ad_sh[t] = a_d[t]; }
    __syncthreads();
    int w = t >> 5, lane = t & 31;
    bool is_conv = w < 4;
    int wr = (w & 3) * 16;
    int r0 = nb + wr;
    if (r0 >= NN) return;  // NN % 16 == 0 -> tiles fully in or fully out
    const float4* __restrict__ wf =
        reinterpret_cast<const float4*>(is_conv ? wf_c : wf_p);
    int tid = lane & 3, gid = lane >> 2;
    float acc[8][4];
#pragma unroll
    for (int n = 0; n < 8; n++)
#pragma unroll
        for (int q = 0; q < 4; q++) acc[n][q] = 0.f;
    int rA0 = (wr + gid) * 68, rA1 = (wr + gid + 8) * 68;
#pragma unroll
    for (int ks = 0; ks < 8; ks++) {
        int c0i = ks * 8 + tid;
        float x0 = Xs[rA0 + c0i];
        float x1 = Xs[rA1 + c0i];
        float x2 = Xs[rA0 + c0i + 4];
        float x3 = Xs[rA1 + c0i + 4];
        unsigned ah0 = cvt_tf32(x0), ah1 = cvt_tf32(x1);
        unsigned ah2 = cvt_tf32(x2), ah3 = cvt_tf32(x3);
        unsigned al0 = cvt_tf32(x0 - __uint_as_float(ah0));
        unsigned al1 = cvt_tf32(x1 - __uint_as_float(ah1));
        unsigned al2 = cvt_tf32(x2 - __uint_as_float(ah2));
        unsigned al3 = cvt_tf32(x3 - __uint_as_float(ah3));
#pragma unroll
        for (int nt = 0; nt < 8; nt++) {
            float4 b = wf[(ks * 8 + nt) * 32 + lane];   // 512B/warp, coalesced
            unsigned bh0 = __float_as_uint(b.x), bh1 = __float_as_uint(b.y);
            unsigned bl0 = __float_as_uint(b.z), bl1 = __float_as_uint(b.w);
            mma_tf32(acc[nt], ah0, ah1, ah2, ah3, bh0, bh1);
            mma_tf32(acc[nt], ah0, ah1, ah2, ah3, bl0, bl1);
            mma_tf32(acc[nt], al0, al1, al2, al3, bh0, bh1);
        }
    }
    // stores: acc[nt][0..1] -> row r0+gid, col pair nt*4+tid; [2..3] -> row +8
    float2* O2 = reinterpret_cast<float2*>(is_conv ? Y : P);
    size_t ra = (size_t)(r0 + gid) * 32 + tid;
    size_t rb = (size_t)(r0 + gid + 8) * 32 + tid;
#pragma unroll
    for (int nt = 0; nt < 8; nt++) {
        O2[ra + nt * 4] = make_float2(acc[nt][0], acc[nt][1]);
        O2[rb + nt * 4] = make_float2(acc[nt][2], acc[nt][3]);
    }
    if (is_conv) {
        float s0 = 0.f, s1 = 0.f, dd0 = 0.f, dd1 = 0.f;
#pragma unroll
        for (int nt = 0; nt < 8; nt++) {
            float sa = as_sh[nt * 8 + 2 * tid], sb = as_sh[nt * 8 + 2 * tid + 1];
            float da = ad_sh[nt * 8 + 2 * tid], db = ad_sh[nt * 8 + 2 * tid + 1];
            s0 += acc[nt][0] * sa + acc[nt][1] * sb;
            s1 += acc[nt][2] * sa + acc[nt][3] * sb;
            dd0 += acc[nt][0] * da + acc[nt][1] * db;
            dd1 += acc[nt][2] * da + acc[nt][3] * db;
        }
        s0 += __shfl_xor_sync(0xffffffffu, s0, 1);
        s0 += __shfl_xor_sync(0xffffffffu, s0, 2);
        s1 += __shfl_xor_sync(0xffffffffu, s1, 1);
        s1 += __shfl_xor_sync(0xffffffffu, s1, 2);
        dd0 += __shfl_xor_sync(0xffffffffu, dd0, 1);
        dd0 += __shfl_xor_sync(0xffffffffu, dd0, 2);
        dd1 += __shfl_xor_sync(0xffffffffu, dd1, 1);
        dd1 += __shfl_xor_sync(0xffffffffu, dd1, 2);
        if (tid == 0) {
            as_o[r0 + gid] = s0;
            ad_o[r0 + gid] = dd0;
            as_o[r0 + gid + 8] = s1;
            ad_o[r0 + gid + 8] = dd1;
        }
    }
}

// ---------------- fused gather-aggregate + softmax + bias/relu/bn(+proj) ------
// One warp per destination node. Half-warps process 2 edges concurrently;
// within a half, lane q (0..15) covers cols [4q, 4q+3] (float4).
template <bool PROJ>
__global__ void __launch_bounds__(256) agg_post(
    const int* __restrict__ roff, const int* __restrict__ cnt,
    const int* __restrict__ esrc, const float* __restrict__ as_,
    const float* __restrict__ ad_, const float* __restrict__ h,
    const float* __restrict__ bias, const float* __restrict__ bg,
    const float* __restrict__ bb, const float* __restrict__ bm,
    const float* __restrict__ bv, const float* __restrict__ proj,
    const float* __restrict__ projb, float* __restrict__ out) {
    int node = (blockIdx.x * blockDim.x + threadIdx.x) >> 5;
    int lane = threadIdx.x & 31;
    if (node >= NN) return;
    int beg = roff[node];
    int m = cnt[node];
    float adn = ad_[node];
    const float4* __restrict__ h4 = reinterpret_cast<const float4*>(h);
    int q = lane & 15, half = lane >> 4;
    float ax = 0.f, ay = 0.f, az = 0.f, aw = 0.f, denom = 0.f;
    for (int base = 0; base < m; base += 32) {
        int rem = m - base;
        int nn = rem < 32 ? rem : 32;
        int s_l = 0;
        float ex_l = 0.f;
        if (lane < nn) {
            s_l = esrc[beg + base + lane];
            float e = as_[s_l] + adn;
            e = e > 0.f ? e : 0.2f * e;
            ex_l = __expf(e);
        }
        denom += ex_l;
#pragma unroll 2
        for (int j = 0; j < nn; j += 2) {
            int jj = j + half;
            int s = __shfl_sync(0xffffffffu, s_l, jj & 31);
            float ex = __shfl_sync(0xffffffffu, ex_l, jj & 31);
            if (jj < nn) {
                float4 hv = h4[(size_t)s * 16 + q];
                ax += ex * hv.x;
                ay += ex * hv.y;
                az += ex * hv.z;
                aw += ex * hv.w;
            }
        }
    }
    // merge the two edge-halves (same columns, disjoint edge subsets)
    ax += __shfl_xor_sync(0xffffffffu, ax, 16);
    ay += __shfl_xor_sync(0xffffffffu, ay, 16);
    az += __shfl_xor_sync(0xffffffffu, az, 16);
    aw += __shfl_xor_sync(0xffffffffu, aw, 16);
#pragma unroll
    for (int o = 16; o; o >>= 1) denom += __shfl_xor_sync(0xffffffffu, denom, o);
    if (half == 0) {
        float inv = 1.f / (denom + 1e-16f);
        float4 b4 = reinterpret_cast<const float4*>(bias)[q];
        float4 g4 = reinterpret_cast<const float4*>(bg)[q];
        float4 be4 = reinterpret_cast<const float4*>(bb)[q];
        float4 m4 = reinterpret_cast<const float4*>(bm)[q];
        float4 v4 = reinterpret_cast<const float4*>(bv)[q];
        float vx = fmaxf(ax * inv + b4.x, 0.f);
        float vy = fmaxf(ay * inv + b4.y, 0.f);
        float vz = fmaxf(az * inv + b4.z, 0.f);
        float vw = fmaxf(aw * inv + b4.w, 0.f);
        vx = (vx - m4.x) * rsqrtf(v4.x + 1e-5f) * g4.x + be4.x;
        vy = (vy - m4.y) * rsqrtf(v4.y + 1e-5f) * g4.y + be4.y;
        vz = (vz - m4.z) * rsqrtf(v4.z + 1e-5f) * g4.z + be4.z;
        vw = (vw - m4.w) * rsqrtf(v4.w + 1e-5f) * g4.w + be4.w;
        if (PROJ) {
            float4 p4 = reinterpret_cast<const float4*>(proj)[(size_t)node * 16 + q];
            float4 pb4 = reinterpret_cast<const float4*>(projb)[q];
            vx += p4.x + pb4.x;
            vy += p4.y + pb4.y;
            vz += p4.z + pb4.z;
            vw += p4.w + pb4.w;
        }
        reinterpret_cast<float4*>(out)[(size_t)node * 16 + q] =
            make_float4(vx, vy, vz, vw);
    }
}

// ---------------- mean pool ----------------
__global__ void zero_gsum(float* __restrict__ g) {
    if (threadIdx.x < HD) g[threadIdx.x] = 0.f;
}
__global__ void __launch_bounds__(256) pool(const float* __restrict__ xp,
                                            float* __restrict__ gsum) {
    int t = threadIdx.x;
    int c = t & 63;
    int row0 = blockIdx.x * 4 + (t >> 6);
    float acc = 0.f;
    for (int n = row0; n < NN; n += gridDim.x * 4) acc += xp[(size_t)n * HD + c];
    atomicAdd(&gsum[c], acc);
}

// ---------------- head MLP ----------------
__global__ void head(const float* __restrict__ gsum, const float* __restrict__ hW1,
                     const float* __restrict__ hb1, const float* __restrict__ hg,
                     const float* __restrict__ hb, const float* __restrict__ hm,
                     const float* __restrict__ hv, const float* __restrict__ hW2,
                     const float* __restrict__ hb2, float* __restrict__ out) {
    __shared__ float g[HD];
    int t = threadIdx.x;
    if (t < HD) g[t] = gsum[t] * (1.f / NN);
    __syncthreads();
    float r = 0.f;
    if (t < 32) {
        float acc = hb1[t];
#pragma unroll
        for (int k = 0; k < HD; k++) acc += g[k] * hW1[k * 32 + t];
        acc = fmaxf(acc, 0.f);
        acc = (acc - hm[t]) * rsqrtf(hv[t] + 1e-5f) * hg[t] + hb[t];
        r = acc * hW2[t];
#pragma unroll
        for (int o = 16; o; o >>= 1) r += __shfl_xor_sync(0xffffffffu, r, o);
        if (t == 0) out[0] = r + hb2[0];
    }
}

// ---------------- launch ----------------
extern "C" void kernel_launch(void* const* d_in, const int* in_sizes, int n_in,
                              void* d_out, int out_size) {
    (void)in_sizes; (void)n_in; (void)out_size;
    const float* x        = (const float*)d_in[0];
    const int*   ei       = (const int*)d_in[1];
    const float* conv1_W  = (const float*)d_in[2];
    const float* conv1_as = (const float*)d_in[3];
    const float* conv1_ad = (const float*)d_in[4];
    const float* conv1_b  = (const float*)d_in[5];
    const float* convW    = (const float*)d_in[6];
    const float* conv_as  = (const float*)d_in[7];
    const float* conv_ad  = (const float*)d_in[8];
    const float* conv_b   = (const float*)d_in[9];
    const float* bn_g     = (const float*)d_in[10];
    const float* bn_b     = (const float*)d_in[11];
    const float* bn_m     = (const float*)d_in[12];
    const float* bn_v     = (const float*)d_in[13];
    const float* projW    = (const float*)d_in[14];
    const float* projb    = (const float*)d_in[15];
    const float* hW1      = (const float*)d_in[16];
    const float* hb1      = (const float*)d_in[17];
    const float* hbn_g    = (const float*)d_in[18];
    const float* hbn_b    = (const float*)d_in[19];
    const float* hbn_m    = (const float*)d_in[20];
    const float* hbn_v    = (const float*)d_in[21];
    const float* hW2      = (const float*)d_in[22];
    const float* hb2      = (const float*)d_in[23];

    const int* src = ei;
    const int* dst = ei + EE;

    float *h, *x1, *x2, *proj, *as_, *ad_, *gsum, *wfrag;
    int *cnt, *roff, *fill, *bsum, *esrc;
    cudaGetSymbolAddress((void**)&h, d_h);
    cudaGetSymbolAddress((void**)&x1, d_x1);
    cudaGetSymbolAddress((void**)&x2, d_x2);
    cudaGetSymbolAddress((void**)&proj, d_proj);
    cudaGetSymbolAddress((void**)&as_, d_as);
    cudaGetSymbolAddress((void**)&ad_, d_ad);
    cudaGetSymbolAddress((void**)&gsum, d_gsum);
    cudaGetSymbolAddress((void**)&cnt, d_cnt);
    cudaGetSymbolAddress((void**)&roff, d_roff);
    cudaGetSymbolAddress((void**)&fill, d_fill);
    cudaGetSymbolAddress((void**)&bsum, d_bsum);
    cudaGetSymbolAddress((void**)&esrc, d_esrc);
    cudaGetSymbolAddress((void**)&wfrag, d_wfrag);

    const int G1 = (NN + 15) / 16;             // gemm1 blocks (16 rows)
    const int GM = (NN + 63) / 64;             // gemm_dual_mma blocks (64 rows)
    const int AB = (NN * 32 + 255) / 256;      // warp-per-node blocks
    const int NB = (NN + 255) / 256;           // node-sized blocks
    const int MB = (TOTE + 255) / 256;         // edge-sized blocks

    // ---- CSR build + W fragment prep (per launch; inputs constant) ----
    zero_cf<<<NB, 256>>>(cnt, fill);
    hist<<<MB, 256>>>(dst, cnt);
    prep_w<<<64, 256>>>(convW, projW, wfrag);
    scan1<<<NB_SCAN, 256>>>(cnt, roff, bsum);
    scan2<<<1, 256>>>(bsum);
    scan3<<<NB_SCAN, 256>>>(roff, bsum);
    scatter<<<MB, 256>>>(src, dst, roff, fill, esrc);

    // ---- layer 1 ----
    gemm1<<<G1, 256>>>(x, conv1_W, h, conv1_as, conv1_ad, as_, ad_);
    agg_post<false><<<AB, 256>>>(roff, cnt, esrc, as_, ad_, h, conv1_b, bn_g,
                                 bn_b, bn_m, bn_v, nullptr, nullptr, x1);

    float* xp = x1;
    float* xn = x2;
    for (int l = 0; l < 4; l++) {
        const float* wf_c = wfrag + (size_t)l * 8 * 8 * 32 * 4;
        const float* wf_p = wfrag + (size_t)(4 + l) * 8 * 8 * 32 * 4;
        gemm_dual_mma<<<GM, 256>>>(xp, wf_c, wf_p, h, proj, conv_as + l * HD,
                                   conv_ad + l * HD, as_, ad_);
        agg_post<true><<<AB, 256>>>(roff, cnt, esrc, as_, ad_, h,
                                    conv_b + l * HD, bn_g + (l + 1) * HD,
                                    bn_b + (l + 1) * HD, bn_m + (l + 1) * HD,
                                    bn_v + (l + 1) * HD, proj, projb + l * HD,
                                    xn);
        float* tmp = xp; xp = xn; xn = tmp;
    }

    zero_gsum<<<1, 64>>>(gsum);
    pool<<<256, 256>>>(xp, gsum);
    head<<<1, 64>>>(gsum, hW1, hb1, hbn_g, hbn_b, hbn_m, hbn_v, hW2, hb2,
                    (float*)d_out);
}

// round 16
// speedup vs baseline: 1.4972x; 1.0361x over previous
#include <cuda_runtime.h>

#define NN 50000
#define EE 800000
#define IND 128
#define HD 64
#define TOTE (EE + NN)
#define NB_SCAN 196   // ceil(NN/256)

// ---------------- scratch (static device memory; no allocations) ----------------
__device__ __align__(256) float d_h[NN * HD];
__device__ __align__(256) float d_x1[NN * HD];
__device__ __align__(256) float d_x2[NN * HD];
__device__ __align__(256) float d_proj[NN * HD];
__device__ __align__(256) float d_as[NN];
__device__ __align__(256) float d_ad[NN];
__device__ __align__(256) float d_gsum[HD];
__device__ __align__(256) int   d_cnt[NN];
__device__ __align__(256) int   d_roff[NN];
__device__ __align__(256) int   d_fill[NN];
__device__ __align__(256) int   d_bsum[NB_SCAN];
__device__ __align__(256) int   d_esrc[TOTE];
// W fragments (layers 2-5): [mat(8)][ks(8)][nt(8)][lane(32)] x float4
__device__ __align__(256) float d_wfrag[8 * 8 * 8 * 32 * 4];
// W fragments (layer 1, K=128): [ks(16)][nt(8)][lane(32)] x float4
__device__ __align__(256) float d_wfrag1[16 * 8 * 32 * 4];

// ---------------- tf32 helpers ----------------
__device__ __forceinline__ unsigned cvt_tf32(float x) {
    unsigned r;
    asm("cvt.rna.tf32.f32 %0, %1;" : "=r"(r) : "f"(x));
    return r;
}
__device__ __forceinline__ void mma_tf32(float* c, unsigned a0, unsigned a1,
                                         unsigned a2, unsigned a3, unsigned b0,
                                         unsigned b1) {
    asm("mma.sync.aligned.m16n8k8.row.col.f32.tf32.tf32.f32 "
        "{%0,%1,%2,%3},{%4,%5,%6,%7},{%8,%9},{%0,%1,%2,%3};"
        : "+f"(c[0]), "+f"(c[1]), "+f"(c[2]), "+f"(c[3])
        : "r"(a0), "r"(a1), "r"(a2), "r"(a3), "r"(b0), "r"(b1));
}

// ---------------- CSR build ----------------
__global__ void __launch_bounds__(256) zero_cf(int* __restrict__ cnt,
                                               int* __restrict__ fill) {
    int i = blockIdx.x * blockDim.x + threadIdx.x;
    if (i < NN) { cnt[i] = 0; fill[i] = 0; }
}

__global__ void __launch_bounds__(256) hist(const int* __restrict__ dst,
                                            int* __restrict__ cnt) {
    int i = blockIdx.x * blockDim.x + threadIdx.x;
    if (i >= TOTE) return;
    int d = (i < EE) ? dst[i] : (i - EE);
    atomicAdd(&cnt[d], 1);
}

__global__ void __launch_bounds__(256) scan1(const int* __restrict__ cnt,
                                             int* __restrict__ roff,
                                             int* __restrict__ bsum) {
    __shared__ int sh[256];
    int t = threadIdx.x;
    int i = blockIdx.x * 256 + t;
    int v = (i < NN) ? cnt[i] : 0;
    sh[t] = v;
    __syncthreads();
#pragma unroll
    for (int o = 1; o < 256; o <<= 1) {
        int u = (t >= o) ? sh[t - o] : 0;
        __syncthreads();
        sh[t] += u;
        __syncthreads();
    }
    if (i < NN) roff[i] = sh[t] - v;           // exclusive
    if (t == 255) bsum[blockIdx.x] = sh[255];  // block total
}

__global__ void __launch_bounds__(256) scan2(int* __restrict__ bsum) {
    __shared__ int sh[256];
    int t = threadIdx.x;
    int v = (t < NB_SCAN) ? bsum[t] : 0;
    sh[t] = v;
    __syncthreads();
#pragma unroll
    for (int o = 1; o < 256; o <<= 1) {
        int u = (t >= o) ? sh[t - o] : 0;
        __syncthreads();
        sh[t] += u;
        __syncthreads();
    }
    if (t < NB_SCAN) bsum[t] = sh[t] - v;      // exclusive over blocks
}

__global__ void __launch_bounds__(256) scan3(int* __restrict__ roff,
                                             const int* __restrict__ bsum) {
    int i = blockIdx.x * blockDim.x + threadIdx.x;
    if (i < NN) roff[i] += bsum[i >> 8];
}

__global__ void __launch_bounds__(256) scatter(const int* __restrict__ src,
                                               const int* __restrict__ dst,
                                               const int* __restrict__ roff,
                                               int* __restrict__ fill,
                                               int* __restrict__ esrc) {
    int i = blockIdx.x * blockDim.x + threadIdx.x;
    if (i >= TOTE) return;
    int s, d;
    if (i < EE) { s = src[i]; d = dst[i]; } else { s = d = i - EE; }
    int pos = roff[d] + atomicAdd(&fill[d], 1);
    esrc[pos] = s;
}

// ---------------- prep W fragments, layers 2-5 ----------------
__global__ void __launch_bounds__(256) prep_w(const float* __restrict__ convW,
                                              const float* __restrict__ projW,
                                              float* __restrict__ wf) {
    int i = blockIdx.x * 256 + threadIdx.x;  // 0 .. 8*8*8*32-1
    if (i >= 8 * 8 * 8 * 32) return;
    int lane = i & 31;
    int nt = (i >> 5) & 7;
    int ks = (i >> 8) & 7;
    int mat = i >> 11;
    int tid = lane & 3, gid = lane >> 2;
    const float* W = (mat < 4) ? convW + mat * HD * HD : projW + (mat - 4) * HD * HD;
    float v0 = W[(ks * 8 + tid) * HD + nt * 8 + gid];
    float v1 = W[(ks * 8 + tid + 4) * HD + nt * 8 + gid];
    unsigned h0 = cvt_tf32(v0), h1 = cvt_tf32(v1);
    unsigned l0 = cvt_tf32(v0 - __uint_as_float(h0));
    unsigned l1 = cvt_tf32(v1 - __uint_as_float(h1));
    reinterpret_cast<float4*>(wf)[i] =
        make_float4(__uint_as_float(h0), __uint_as_float(h1),
                    __uint_as_float(l0), __uint_as_float(l1));
}

// ---------------- prep W fragments, layer 1 (K=128, 16 ks) ----------------
__global__ void __launch_bounds__(256) prep_w1(const float* __restrict__ W,
                                               float* __restrict__ wf) {
    int i = blockIdx.x * 256 + threadIdx.x;  // 0 .. 16*8*32-1 = 4095
    if (i >= 16 * 8 * 32) return;
    int lane = i & 31;
    int nt = (i >> 5) & 7;
    int ks = i >> 8;                          // 0..15
    int tid = lane & 3, gid = lane >> 2;
    float v0 = W[(ks * 8 + tid) * HD + nt * 8 + gid];
    float v1 = W[(ks * 8 + tid + 4) * HD + nt * 8 + gid];
    unsigned h0 = cvt_tf32(v0), h1 = cvt_tf32(v1);
    unsigned l0 = cvt_tf32(v0 - __uint_as_float(h0));
    unsigned l1 = cvt_tf32(v1 - __uint_as_float(h1));
    reinterpret_cast<float4*>(wf)[i] =
        make_float4(__uint_as_float(h0), __uint_as_float(h1),
                    __uint_as_float(l0), __uint_as_float(l1));
}

// ---------------- layer-1 GEMM via tf32 mma (K=128, 2 K-stages) ----------
// 128 rows/block, 8 warps x 16-row tiles. X staged 64 K-cols at a time.
__global__ void __launch_bounds__(256) gemm1_mma(
    const float* __restrict__ X, const float* __restrict__ wf1,
    float* __restrict__ Y, const float* __restrict__ a_s,
    const float* __restrict__ a_d, float* __restrict__ as_o,
    float* __restrict__ ad_o) {
    __shared__ float Xs[128 * 68];   // 34.8KB, stride-68 conflict-free
    __shared__ float as_sh[HD], ad_sh[HD];
    int t = threadIdx.x;
    int nb = blockIdx.x * 128;
    if (t < HD) { as_sh[t] = a_s[t]; ad_sh[t] = a_d[t]; }
    int w = t >> 5, lane = t & 31;
    int wr = w * 16;
    int r0 = nb + wr;
    int tid = lane & 3, gid = lane >> 2;
    const float4* __restrict__ wf = reinterpret_cast<const float4*>(wf1);
    float acc[8][4];
#pragma unroll
    for (int n = 0; n < 8; n++)
#pragma unroll
        for (int q = 0; q < 4; q++) acc[n][q] = 0.f;
    int rA0 = (wr + gid) * 68, rA1 = (wr + gid + 8) * 68;
#pragma unroll
    for (int stage = 0; stage < 2; stage++) {
        // stage K-cols [stage*64, stage*64+64)
        for (int i = t; i < 128 * 64; i += 256) {
            int r = i >> 6, c = i & 63;
            int node = nb + r;
            Xs[r * 68 + c] =
                (node < NN) ? X[(size_t)node * IND + stage * 64 + c] : 0.f;
        }
        __syncthreads();
#pragma unroll
        for (int ksl = 0; ksl < 8; ksl++) {
            int ks = stage * 8 + ksl;
            int c0i = ksl * 8 + tid;
            float x0 = Xs[rA0 + c0i];
            float x1 = Xs[rA1 + c0i];
            float x2 = Xs[rA0 + c0i + 4];
            float x3 = Xs[rA1 + c0i + 4];
            unsigned ah0 = cvt_tf32(x0), ah1 = cvt_tf32(x1);
            unsigned ah2 = cvt_tf32(x2), ah3 = cvt_tf32(x3);
            unsigned al0 = cvt_tf32(x0 - __uint_as_float(ah0));
            unsigned al1 = cvt_tf32(x1 - __uint_as_float(ah1));
            unsigned al2 = cvt_tf32(x2 - __uint_as_float(ah2));
            unsigned al3 = cvt_tf32(x3 - __uint_as_float(ah3));
#pragma unroll
            for (int nt = 0; nt < 8; nt++) {
                float4 b = wf[(ks * 8 + nt) * 32 + lane];
                unsigned bh0 = __float_as_uint(b.x), bh1 = __float_as_uint(b.y);
                unsigned bl0 = __float_as_uint(b.z), bl1 = __float_as_uint(b.w);
                mma_tf32(acc[nt], ah0, ah1, ah2, ah3, bh0, bh1);
                mma_tf32(acc[nt], ah0, ah1, ah2, ah3, bl0, bl1);
                mma_tf32(acc[nt], al0, al1, al2, al3, bh0, bh1);
            }
        }
        __syncthreads();
    }
    if (r0 >= NN) return;   // tail: 16-row tiles fully in or out (NN%16==0)
    float2* Y2 = reinterpret_cast<float2*>(Y);
    size_t ra = (size_t)(r0 + gid) * 32 + tid;
    size_t rb = (size_t)(r0 + gid + 8) * 32 + tid;
#pragma unroll
    for (int nt = 0; nt < 8; nt++) {
        Y2[ra + nt * 4] = make_float2(acc[nt][0], acc[nt][1]);
        Y2[rb + nt * 4] = make_float2(acc[nt][2], acc[nt][3]);
    }
    float s0 = 0.f, s1 = 0.f, dd0 = 0.f, dd1 = 0.f;
#pragma unroll
    for (int nt = 0; nt < 8; nt++) {
        float sa = as_sh[nt * 8 + 2 * tid], sb = as_sh[nt * 8 + 2 * tid + 1];
        float da = ad_sh[nt * 8 + 2 * tid], db = ad_sh[nt * 8 + 2 * tid + 1];
        s0 += acc[nt][0] * sa + acc[nt][1] * sb;
        s1 += acc[nt][2] * sa + acc[nt][3] * sb;
        dd0 += acc[nt][0] * da + acc[nt][1] * db;
        dd1 += acc[nt][2] * da + acc[nt][3] * db;
    }
    s0 += __shfl_xor_sync(0xffffffffu, s0, 1);
    s0 += __shfl_xor_sync(0xffffffffu, s0, 2);
    s1 += __shfl_xor_sync(0xffffffffu, s1, 1);
    s1 += __shfl_xor_sync(0xffffffffu, s1, 2);
    dd0 += __shfl_xor_sync(0xffffffffu, dd0, 1);
    dd0 += __shfl_xor_sync(0xffffffffu, dd0, 2);
    dd1 += __shfl_xor_sync(0xffffffffu, dd1, 1);
    dd1 += __shfl_xor_sync(0xffffffffu, dd1, 2);
    if (tid == 0) {
        as_o[r0 + gid] = s0;
        ad_o[r0 + gid] = dd0;
        as_o[r0 + gid + 8] = s1;
        ad_o[r0 + gid + 8] = dd1;
    }
}

// ---------------- dual GEMM via tf32 mma (layers 2-5) ----------------
// 64 rows/block, 256 threads. Warps 0-3: conv (+scores); warps 4-7: proj.
__global__ void __launch_bounds__(256) gemm_dual_mma(
    const float* __restrict__ X, const float* __restrict__ wf_c,
    const float* __restrict__ wf_p, float* __restrict__ Y,
    float* __restrict__ P, const float* __restrict__ a_s,
    const float* __restrict__ a_d, float* __restrict__ as_o,
    float* __restrict__ ad_o) {
    __shared__ float Xs[64 * 68];    // padded stride 68, ~17.4KB
    __shared__ float as_sh[HD], ad_sh[HD];
    int t = threadIdx.x;
    int nb = blockIdx.x * 64;
    for (int i = t; i < 64 * 64; i += 256) {
        int r = i >> 6, c = i & 63;
        int node = nb + r;
        Xs[r * 68 + c] = (node < NN) ? X[(size_t)node * HD + c] : 0.f;
    }
    if (t < HD) { as_sh[t] = a_s[t]; ad_sh[t] = a_d[t]; }
    __syncthreads();
    int w = t >> 5, lane = t & 31;
    bool is_conv = w < 4;
    int wr = (w & 3) * 16;
    int r0 = nb + wr;
    if (r0 >= NN) return;  // NN % 16 == 0 -> tiles fully in or fully out
    const float4* __restrict__ wf =
        reinterpret_cast<const float4*>(is_conv ? wf_c : wf_p);
    int tid = lane & 3, gid = lane >> 2;
    float acc[8][4];
#pragma unroll
    for (int n = 0; n < 8; n++)
#pragma unroll
        for (int q = 0; q < 4; q++) acc[n][q] = 0.f;
    int rA0 = (wr + gid) * 68, rA1 = (wr + gid + 8) * 68;
#pragma unroll
    for (int ks = 0; ks < 8; ks++) {
        int c0i = ks * 8 + tid;
        float x0 = Xs[rA0 + c0i];
        float x1 = Xs[rA1 + c0i];
        float x2 = Xs[rA0 + c0i + 4];
        float x3 = Xs[rA1 + c0i + 4];
        unsigned ah0 = cvt_tf32(x0), ah1 = cvt_tf32(x1);
        unsigned ah2 = cvt_tf32(x2), ah3 = cvt_tf32(x3);
        unsigned al0 = cvt_tf32(x0 - __uint_as_float(ah0));
        unsigned al1 = cvt_tf32(x1 - __uint_as_float(ah1));
        unsigned al2 = cvt_tf32(x2 - __uint_as_float(ah2));
        unsigned al3 = cvt_tf32(x3 - __uint_as_float(ah3));
#pragma unroll
        for (int nt = 0; nt < 8; nt++) {
            float4 b = wf[(ks * 8 + nt) * 32 + lane];   // 512B/warp, coalesced
            unsigned bh0 = __float_as_uint(b.x), bh1 = __float_as_uint(b.y);
            unsigned bl0 = __float_as_uint(b.z), bl1 = __float_as_uint(b.w);
            mma_tf32(acc[nt], ah0, ah1, ah2, ah3, bh0, bh1);
            mma_tf32(acc[nt], ah0, ah1, ah2, ah3, bl0, bl1);
            mma_tf32(acc[nt], al0, al1, al2, al3, bh0, bh1);
        }
    }
    float2* O2 = reinterpret_cast<float2*>(is_conv ? Y : P);
    size_t ra = (size_t)(r0 + gid) * 32 + tid;
    size_t rb = (size_t)(r0 + gid + 8) * 32 + tid;
#pragma unroll
    for (int nt = 0; nt < 8; nt++) {
        O2[ra + nt * 4] = make_float2(acc[nt][0], acc[nt][1]);
        O2[rb + nt * 4] = make_float2(acc[nt][2], acc[nt][3]);
    }
    if (is_conv) {
        float s0 = 0.f, s1 = 0.f, dd0 = 0.f, dd1 = 0.f;
#pragma unroll
        for (int nt = 0; nt < 8; nt++) {
            float sa = as_sh[nt * 8 + 2 * tid], sb = as_sh[nt * 8 + 2 * tid + 1];
            float da = ad_sh[nt * 8 + 2 * tid], db = ad_sh[nt * 8 + 2 * tid + 1];
            s0 += acc[nt][0] * sa + acc[nt][1] * sb;
            s1 += acc[nt][2] * sa + acc[nt][3] * sb;
            dd0 += acc[nt][0] * da + acc[nt][1] * db;
            dd1 += acc[nt][2] * da + acc[nt][3] * db;
        }
        s0 += __shfl_xor_sync(0xffffffffu, s0, 1);
        s0 += __shfl_xor_sync(0xffffffffu, s0, 2);
        s1 += __shfl_xor_sync(0xffffffffu, s1, 1);
        s1 += __shfl_xor_sync(0xffffffffu, s1, 2);
        dd0 += __shfl_xor_sync(0xffffffffu, dd0, 1);
        dd0 += __shfl_xor_sync(0xffffffffu, dd0, 2);
        dd1 += __shfl_xor_sync(0xffffffffu, dd1, 1);
        dd1 += __shfl_xor_sync(0xffffffffu, dd1, 2);
        if (tid == 0) {
            as_o[r0 + gid] = s0;
            ad_o[r0 + gid] = dd0;
            as_o[r0 + gid + 8] = s1;
            ad_o[r0 + gid + 8] = dd1;
        }
    }
}

// ---------------- fused gather-aggregate + softmax + bias/relu/bn(+proj) ------
// One warp per destination node. Half-warps process 2 edges concurrently;
// within a half, lane q (0..15) covers cols [4q, 4q+3] (float4).
template <bool PROJ>
__global__ void __launch_bounds__(256) agg_post(
    const int* __restrict__ roff, const int* __restrict__ cnt,
    const int* __restrict__ esrc, const float* __restrict__ as_,
    const float* __restrict__ ad_, const float* __restrict__ h,
    const float* __restrict__ bias, const float* __restrict__ bg,
    const float* __restrict__ bb, const float* __restrict__ bm,
    const float* __restrict__ bv, const float* __restrict__ proj,
    const float* __restrict__ projb, float* __restrict__ out) {
    int node = (blockIdx.x * blockDim.x + threadIdx.x) >> 5;
    int lane = threadIdx.x & 31;
    if (node >= NN) return;
    int beg = roff[node];
    int m = cnt[node];
    float adn = ad_[node];
    const float4* __restrict__ h4 = reinterpret_cast<const float4*>(h);
    int q = lane & 15, half = lane >> 4;
    float ax = 0.f, ay = 0.f, az = 0.f, aw = 0.f, denom = 0.f;
    for (int base = 0; base < m; base += 32) {
        int rem = m - base;
        int nn = rem < 32 ? rem : 32;
        int s_l = 0;
        float ex_l = 0.f;
        if (lane < nn) {
            s_l = esrc[beg + base + lane];
            float e = as_[s_l] + adn;
            e = e > 0.f ? e : 0.2f * e;
            ex_l = __expf(e);
        }
        denom += ex_l;
#pragma unroll 2
        for (int j = 0; j < nn; j += 2) {
            int jj = j + half;
            int s = __shfl_sync(0xffffffffu, s_l, jj & 31);
            float ex = __shfl_sync(0xffffffffu, ex_l, jj & 31);
            if (jj < nn) {
                float4 hv = h4[(size_t)s * 16 + q];
                ax += ex * hv.x;
                ay += ex * hv.y;
                az += ex * hv.z;
                aw += ex * hv.w;
            }
        }
    }
    // merge the two edge-halves (same columns, disjoint edge subsets)
    ax += __shfl_xor_sync(0xffffffffu, ax, 16);
    ay += __shfl_xor_sync(0xffffffffu, ay, 16);
    az += __shfl_xor_sync(0xffffffffu, az, 16);
    aw += __shfl_xor_sync(0xffffffffu, aw, 16);
#pragma unroll
    for (int o = 16; o; o >>= 1) denom += __shfl_xor_sync(0xffffffffu, denom, o);
    if (half == 0) {
        float inv = 1.f / (denom + 1e-16f);
        float4 b4 = reinterpret_cast<const float4*>(bias)[q];
        float4 g4 = reinterpret_cast<const float4*>(bg)[q];
        float4 be4 = reinterpret_cast<const float4*>(bb)[q];
        float4 m4 = reinterpret_cast<const float4*>(bm)[q];
        float4 v4 = reinterpret_cast<const float4*>(bv)[q];
        float vx = fmaxf(ax * inv + b4.x, 0.f);
        float vy = fmaxf(ay * inv + b4.y, 0.f);
        float vz = fmaxf(az * inv + b4.z, 0.f);
        float vw = fmaxf(aw * inv + b4.w, 0.f);
        vx = (vx - m4.x) * rsqrtf(v4.x + 1e-5f) * g4.x + be4.x;
        vy = (vy - m4.y) * rsqrtf(v4.y + 1e-5f) * g4.y + be4.y;
        vz = (vz - m4.z) * rsqrtf(v4.z + 1e-5f) * g4.z + be4.z;
        vw = (vw - m4.w) * rsqrtf(v4.w + 1e-5f) * g4.w + be4.w;
        if (PROJ) {
            float4 p4 = reinterpret_cast<const float4*>(proj)[(size_t)node * 16 + q];
            float4 pb4 = reinterpret_cast<const float4*>(projb)[q];
            vx += p4.x + pb4.x;
            vy += p4.y + pb4.y;
            vz += p4.z + pb4.z;
            vw += p4.w + pb4.w;
        }
        reinterpret_cast<float4*>(out)[(size_t)node * 16 + q] =
            make_float4(vx, vy, vz, vw);
    }
}

// ---------------- mean pool ----------------
__global__ void zero_gsum(float* __restrict__ g) {
    if (threadIdx.x < HD) g[threadIdx.x] = 0.f;
}
__global__ void __launch_bounds__(256) pool(const float* __restrict__ xp,
                                            float* __restrict__ gsum) {
    int t = threadIdx.x;
    int c = t & 63;
    int row0 = blockIdx.x * 4 + (t >> 6);
    float acc = 0.f;
    for (int n = row0; n < NN; n += gridDim.x * 4) acc += xp[(size_t)n * HD + c];
    atomicAdd(&gsum[c], acc);
}

// ---------------- head MLP ----------------
__global__ void head(const float* __restrict__ gsum, const float* __restrict__ hW1,
                     const float* __restrict__ hb1, const float* __restrict__ hg,
                     const float* __restrict__ hb, const float* __restrict__ hm,
                     const float* __restrict__ hv, const float* __restrict__ hW2,
                     const float* __restrict__ hb2, float* __restrict__ out) {
    __shared__ float g[HD];
    int t = threadIdx.x;
    if (t < HD) g[t] = gsum[t] * (1.f / NN);
    __syncthreads();
    float r = 0.f;
    if (t < 32) {
        float acc = hb1[t];
#pragma unroll
        for (int k = 0; k < HD; k++) acc += g[k] * hW1[k * 32 + t];
        acc = fmaxf(acc, 0.f);
        acc = (acc - hm[t]) * rsqrtf(hv[t] + 1e-5f) * hg[t] + hb[t];
        r = acc * hW2[t];
#pragma unroll
        for (int o = 16; o; o >>= 1) r += __shfl_xor_sync(0xffffffffu, r, o);
        if (t == 0) out[0] = r + hb2[0];
    }
}

// ---------------- launch ----------------
extern "C" void kernel_launch(void* const* d_in, const int* in_sizes, int n_in,
                              void* d_out, int out_size) {
    (void)in_sizes; (void)n_in; (void)out_size;
    const float* x        = (const float*)d_in[0];
    const int*   ei       = (const int*)d_in[1];
    const float* conv1_W  = (const float*)d_in[2];
    const float* conv1_as = (const float*)d_in[3];
    const float* conv1_ad = (const float*)d_in[4];
    const float* conv1_b  = (const float*)d_in[5];
    const float* convW    = (const float*)d_in[6];
    const float* conv_as  = (const float*)d_in[7];
    const float* conv_ad  = (const float*)d_in[8];
    const float* conv_b   = (const float*)d_in[9];
    const float* bn_g     = (const float*)d_in[10];
    const float* bn_b     = (const float*)d_in[11];
    const float* bn_m     = (const float*)d_in[12];
    const float* bn_v     = (const float*)d_in[13];
    const float* projW    = (const float*)d_in[14];
    const float* projb    = (const float*)d_in[15];
    const float* hW1      = (const float*)d_in[16];
    const float* hb1      = (const float*)d_in[17];
    const float* hbn_g    = (const float*)d_in[18];
    const float* hbn_b    = (const float*)d_in[19];
    const float* hbn_m    = (const float*)d_in[20];
    const float* hbn_v    = (const float*)d_in[21];
    const float* hW2      = (const float*)d_in[22];
    const float* hb2      = (const float*)d_in[23];

    const int* src = ei;
    const int* dst = ei + EE;

    float *h, *x1, *x2, *proj, *as_, *ad_, *gsum, *wfrag, *wfrag1;
    int *cnt, *roff, *fill, *bsum, *esrc;
    cudaGetSymbolAddress((void**)&h, d_h);
    cudaGetSymbolAddress((void**)&x1, d_x1);
    cudaGetSymbolAddress((void**)&x2, d_x2);
    cudaGetSymbolAddress((void**)&proj, d_proj);
    cudaGetSymbolAddress((void**)&as_, d_as);
    cudaGetSymbolAddress((void**)&ad_, d_ad);
    cudaGetSymbolAddress((void**)&gsum, d_gsum);
    cudaGetSymbolAddress((void**)&cnt, d_cnt);
    cudaGetSymbolAddress((void**)&roff, d_roff);
    cudaGetSymbolAddress((void**)&fill, d_fill);
    cudaGetSymbolAddress((void**)&bsum, d_bsum);
    cudaGetSymbolAddress((void**)&esrc, d_esrc);
    cudaGetSymbolAddress((void**)&wfrag, d_wfrag);
    cudaGetSymbolAddress((void**)&wfrag1, d_wfrag1);

    const int G1 = (NN + 127) / 128;           // gemm1_mma blocks (128 rows)
    const int GM = (NN + 63) / 64;             // gemm_dual_mma blocks (64 rows)
    const int AB = (NN * 32 + 255) / 256;      // warp-per-node blocks
    const int NB = (NN + 255) / 256;           // node-sized blocks
    const int MB = (TOTE + 255) / 256;         // edge-sized blocks

    // ---- CSR build + W fragment prep (per launch; inputs constant) ----
    zero_cf<<<NB, 256>>>(cnt, fill);
    hist<<<MB, 256>>>(dst, cnt);
    prep_w<<<64, 256>>>(convW, projW, wfrag);
    prep_w1<<<16, 256>>>(conv1_W, wfrag1);
    scan1<<<NB_SCAN, 256>>>(cnt, roff, bsum);
    scan2<<<1, 256>>>(bsum);
    scan3<<<NB_SCAN, 256>>>(roff, bsum);
    scatter<<<MB, 256>>>(src, dst, roff, fill, esrc);

    // ---- layer 1 ----
    gemm1_mma<<<G1, 256>>>(x, wfrag1, h, conv1_as, conv1_ad, as_, ad_);
    agg_post<false><<<AB, 256>>>(roff, cnt, esrc, as_, ad_, h, conv1_b, bn_g,
                                 bn_b, bn_m, bn_v, nullptr, nullptr, x1);

    float* xp = x1;
    float* xn = x2;
    for (int l = 0; l < 4; l++) {
        const float* wf_c = wfrag + (size_t)l * 8 * 8 * 32 * 4;
        const float* wf_p = wfrag + (size_t)(4 + l) * 8 * 8 * 32 * 4;
        gemm_dual_mma<<<GM, 256>>>(xp, wf_c, wf_p, h, proj, conv_as + l * HD,
                                   conv_ad + l * HD, as_, ad_);
        agg_post<true><<<AB, 256>>>(roff, cnt, esrc, as_, ad_, h,
                                    conv_b + l * HD, bn_g + (l + 1) * HD,
                                    bn_b + (l + 1) * HD, bn_m + (l + 1) * HD,
                                    bn_v + (l + 1) * HD, proj, projb + l * HD,
                                    xn);
        float* tmp = xp; xp = xn; xn = tmp;
    }

    zero_gsum<<<1, 64>>>(gsum);
    pool<<<256, 256>>>(xp, gsum);
    head<<<1, 64>>>(gsum, hW1, hb1, hbn_g, hbn_b, hbn_m, hbn_v, hW2, hb2,
                    (float*)d_out);
}